// round 4
// baseline (speedup 1.0000x reference)
#include <cuda_runtime.h>
#include <cuda_bf16.h>
#include <cstdint>
#include <cstddef>

// ===========================================================================
// InvariantReadout — bf16-split mma.sync (HMMA) pipeline, round 4
//   h1 = silu(X@W1+b1); h2 = silu(h1@W2+b2); x = h2@W3+b3
//   logits = silu(X@aW1+ab1)@aW2 + ab2  (fused into attention GEMM epilogue)
//   per-segment softmax -> weighted segment sum -> (G, 256)
// fp32 split to bf16 hi/lo; D = Ahi*Bhi + Ahi*Blo + Alo*Bhi (err ~2^-16).
// BN=256 (full width): A read once per GEMM. 512 threads, 16 warps.
// ===========================================================================

#define NMAX 200000
#define DIM  256
#define BM   128
#define BN   256
#define BKT  64                        // bf16 k per stage (128 B rows)
#define KTILES (DIM / BKT)             // 4
#define A_HALF  (128 * 128)            // 16 KB (one A operand half)
#define B_HALF  (256 * 128)            // 32 KB (one B operand half)
#define STAGE_BYTES (2 * A_HALF + 2 * B_HALF)   // 96 KB
#define DYN_SMEM (2 * STAGE_BYTES)              // 192 KB
#define OFF_AHI 0
#define OFF_ALO (A_HALF)
#define OFF_BHI (2 * A_HALF)
#define OFF_BLO (2 * A_HALF + B_HALF)

// modes for gemm epilogue
#define MODE_SPLIT 0   // silu + split -> bf16 hi/lo
#define MODE_F32   1   // plain bias -> fp32
#define MODE_ATT   2   // silu, dot with aW2, reduce -> logits (no C write)

// ---------------- scratch (__device__ globals: allocation-free rule) -------
__device__ __nv_bfloat16 g_Xhi[(size_t)NMAX * DIM];
__device__ __nv_bfloat16 g_Xlo[(size_t)NMAX * DIM];
__device__ __nv_bfloat16 g_Ahi[(size_t)NMAX * DIM];
__device__ __nv_bfloat16 g_Alo[(size_t)NMAX * DIM];
__device__ __nv_bfloat16 g_Bhi[(size_t)NMAX * DIM];
__device__ __nv_bfloat16 g_Blo[(size_t)NMAX * DIM];
__device__ float         g_f[(size_t)NMAX * DIM];   // fp32 x
__device__ float         g_logits[NMAX];
__device__ __nv_bfloat16 g_Wt[8][DIM * DIM];        // {W1,W2,W3,aW1} x {hi,lo}

// ---------------- helpers ---------------------------------------------------
__device__ __forceinline__ uint32_t smem_u32(const void* p) {
    uint32_t a;
    asm("{ .reg .u64 t; cvta.to.shared.u64 t, %1; cvt.u32.u64 %0, t; }" : "=r"(a) : "l"(p));
    return a;
}
__device__ __forceinline__ void cp16(uint32_t dst, const void* src) {
    asm volatile("cp.async.cg.shared.global [%0], [%1], 16;" :: "r"(dst), "l"(src) : "memory");
}
__device__ __forceinline__ void cp_commit() {
    asm volatile("cp.async.commit_group;" ::: "memory");
}
template <int NW>
__device__ __forceinline__ void cp_wait() {
    asm volatile("cp.async.wait_group %0;" :: "n"(NW) : "memory");
}
__device__ __forceinline__ void ldsm4(uint32_t* r, uint32_t addr) {
    asm volatile("ldmatrix.sync.aligned.m8n8.x4.shared.b16 {%0,%1,%2,%3}, [%4];"
                 : "=r"(r[0]), "=r"(r[1]), "=r"(r[2]), "=r"(r[3]) : "r"(addr));
}
__device__ __forceinline__ void mma16816(float* d, const uint32_t* a, const uint32_t* b) {
    asm volatile(
        "mma.sync.aligned.m16n8k16.row.col.f32.bf16.bf16.f32 "
        "{%0,%1,%2,%3}, {%4,%5,%6,%7}, {%8,%9}, {%0,%1,%2,%3};"
        : "+f"(d[0]), "+f"(d[1]), "+f"(d[2]), "+f"(d[3])
        : "r"(a[0]), "r"(a[1]), "r"(a[2]), "r"(a[3]), "r"(b[0]), "r"(b[1]));
}
__device__ __forceinline__ float silu_f(float x) { return x / (1.0f + __expf(-x)); }
__device__ __forceinline__ void split1(float v, uint16_t& h, uint16_t& l) {
    __nv_bfloat16 hb = __float2bfloat16(v);
    float hf = __bfloat162float(hb);
    __nv_bfloat16 lb = __float2bfloat16(v - hf);
    h = __bfloat16_as_ushort(hb);
    l = __bfloat16_as_ushort(lb);
}

// ---------------- prep kernels ---------------------------------------------
__global__ __launch_bounds__(256) void xsplit_kernel(
    const float4* __restrict__ X, uint2* __restrict__ hi, uint2* __restrict__ lo, int n4)
{
    int i = blockIdx.x * 256 + threadIdx.x;
    if (i >= n4) return;
    float4 v = X[i];
    uint16_t h0,l0,h1,l1,h2,l2,h3,l3;
    split1(v.x,h0,l0); split1(v.y,h1,l1); split1(v.z,h2,l2); split1(v.w,h3,l3);
    hi[i] = make_uint2((uint32_t)h0 | ((uint32_t)h1<<16), (uint32_t)h2 | ((uint32_t)h3<<16));
    lo[i] = make_uint2((uint32_t)l0 | ((uint32_t)l1<<16), (uint32_t)l2 | ((uint32_t)l3<<16));
}

// all 4 weights: transpose + split W[k][n] -> hi/lo[n][k] (n-major)
__global__ __launch_bounds__(256) void wsplit_all_kernel(
    const float* __restrict__ W1, const float* __restrict__ W2,
    const float* __restrict__ W3, const float* __restrict__ WA,
    __nv_bfloat16* __restrict__ Wt)
{
    int n = blockIdx.x, k = threadIdx.x, w = blockIdx.y;
    const float* W = (w == 0) ? W1 : (w == 1) ? W2 : (w == 2) ? W3 : WA;
    float v = W[k * DIM + n];
    uint16_t h, l; split1(v, h, l);
    Wt[(size_t)(2 * w)     * DIM * DIM + n * DIM + k] = __ushort_as_bfloat16(h);
    Wt[(size_t)(2 * w + 1) * DIM * DIM + n * DIM + k] = __ushort_as_bfloat16(l);
}

// ---------------- mma.sync GEMM ---------------------------------------------
// C(nRows x 256) = epi(A @ W + bias); A = (Ahi,Alo) row-major [m][k],
// W = (Bhi,Blo) n-major [n][k] (= col-major B).
template <int MODE>
__global__ __launch_bounds__(512) void gemm_mma(
    const __nv_bfloat16* __restrict__ Ahi, const __nv_bfloat16* __restrict__ Alo,
    const __nv_bfloat16* __restrict__ Bhi, const __nv_bfloat16* __restrict__ Blo,
    const float* __restrict__ bias,
    float* __restrict__ Cf, __nv_bfloat16* __restrict__ Chi, __nv_bfloat16* __restrict__ Clo,
    const float* __restrict__ aW2, const float* __restrict__ ab2,
    float* __restrict__ logits, int nRows)
{
    extern __shared__ char sm[];
    __shared__ float s_bias[BN];
    __shared__ float s_aw2[BN];
    __shared__ float s_part[4][BM];

    const int tid  = threadIdx.x;
    const int wid  = tid >> 5;
    const int lane = tid & 31;
    const int warp_m = wid >> 2;      // 0..3 -> 32-row slab
    const int warp_n = wid & 3;       // 0..3 -> 64-col slab
    const int rowBase = blockIdx.x * BM;

    if (tid < BN) {
        s_bias[tid] = bias[tid];
        if (MODE == MODE_ATT) s_aw2[tid] = aW2[tid];
    }

    const uint32_t smb = smem_u32(sm);

    auto load_stage = [&](int s, int kt) {
        const uint32_t st = smb + s * STAGE_BYTES;
        const int ke = kt * BKT;
        #pragma unroll
        for (int i = 0; i < 2; i++) {                  // A hi+lo: 128 rows
            int f = tid + i * 512;
            int r = f >> 3, c = f & 7;
            uint32_t off = (uint32_t)(r * 128 + ((c ^ (r & 7)) << 4));
            int gr = rowBase + r; if (gr >= nRows) gr = nRows - 1;
            size_t ga = (size_t)gr * DIM + ke + c * 8;
            cp16(st + OFF_AHI + off, Ahi + ga);
            cp16(st + OFF_ALO + off, Alo + ga);
        }
        #pragma unroll
        for (int i = 0; i < 4; i++) {                  // B hi+lo: 256 rows
            int f = tid + i * 512;
            int r = f >> 3, c = f & 7;
            uint32_t off = (uint32_t)(r * 128 + ((c ^ (r & 7)) << 4));
            size_t gb = (size_t)r * DIM + ke + c * 8;
            cp16(st + OFF_BHI + off, Bhi + gb);
            cp16(st + OFF_BLO + off, Blo + gb);
        }
        cp_commit();
    };

    float acc[2][8][4];
    #pragma unroll
    for (int mt = 0; mt < 2; mt++)
        #pragma unroll
        for (int j = 0; j < 8; j++)
            #pragma unroll
            for (int q = 0; q < 4; q++) acc[mt][j][q] = 0.f;

    const int rrA = (lane & 7) + ((lane >> 3) & 1) * 8;
    const int khA = lane >> 4;
    const int rrB = (lane & 7) + (lane >> 4) * 8;
    const int khB = (lane >> 3) & 1;

    load_stage(0, 0);

    for (int kt = 0; kt < KTILES; kt++) {
        if (kt > 0) __syncthreads();
        if (kt + 1 < KTILES) load_stage((kt + 1) & 1, kt + 1);
        else cp_commit();
        cp_wait<1>();
        __syncthreads();

        const uint32_t base = smb + (kt & 1) * STAGE_BYTES;

        #pragma unroll
        for (int ks = 0; ks < 4; ks++) {
            uint32_t ah[2][4], al[2][4];
            #pragma unroll
            for (int mt = 0; mt < 2; mt++) {
                int row = warp_m * 32 + mt * 16 + rrA;
                uint32_t a = base + row * 128 + (((ks * 2 + khA) ^ (row & 7)) << 4);
                ldsm4(ah[mt], a + OFF_AHI);
                ldsm4(al[mt], a + OFF_ALO);
            }
            #pragma unroll
            for (int nt = 0; nt < 4; nt++) {
                int row = warp_n * 64 + nt * 16 + rrB;
                uint32_t a = base + OFF_BHI + row * 128
                           + (((ks * 2 + khB) ^ (row & 7)) << 4);
                uint32_t bh[4], bl[4];
                ldsm4(bh, a);
                ldsm4(bl, a + B_HALF);
                #pragma unroll
                for (int mt = 0; mt < 2; mt++)
                    #pragma unroll
                    for (int h = 0; h < 2; h++) {
                        float* d = acc[mt][nt * 2 + h];
                        mma16816(d, ah[mt], &bh[h * 2]);   // hi*hi
                        mma16816(d, ah[mt], &bl[h * 2]);   // hi*lo
                        mma16816(d, al[mt], &bh[h * 2]);   // lo*hi
                    }
            }
        }
    }

    // ---- epilogue ----
    const int g  = lane >> 2;
    const int cp = (lane & 3) * 2;

    if (MODE == MODE_ATT) {
        // silu, dot with aW2, reduce to per-row logit. Deterministic reduction.
        float part[2][2] = {{0.f, 0.f}, {0.f, 0.f}};
        #pragma unroll
        for (int mt = 0; mt < 2; mt++)
            #pragma unroll
            for (int j = 0; j < 8; j++) {
                int lc = warp_n * 64 + j * 8 + cp;
                float bz0 = s_bias[lc], bz1 = s_bias[lc + 1];
                float w0 = s_aw2[lc],  w1 = s_aw2[lc + 1];
                #pragma unroll
                for (int hrow = 0; hrow < 2; hrow++) {
                    float v0 = silu_f(acc[mt][j][hrow * 2]     + bz0);
                    float v1 = silu_f(acc[mt][j][hrow * 2 + 1] + bz1);
                    part[mt][hrow] += v0 * w0 + v1 * w1;
                }
            }
        #pragma unroll
        for (int mt = 0; mt < 2; mt++)
            #pragma unroll
            for (int hrow = 0; hrow < 2; hrow++) {
                float p = part[mt][hrow];
                p += __shfl_xor_sync(0xFFFFFFFFu, p, 1);
                p += __shfl_xor_sync(0xFFFFFFFFu, p, 2);
                if ((lane & 3) == 0)
                    s_part[warp_n][warp_m * 32 + mt * 16 + hrow * 8 + g] = p;
            }
        __syncthreads();
        if (tid < BM) {
            int row = rowBase + tid;
            if (row < nRows) {
                logits[row] = s_part[0][tid] + s_part[1][tid]
                            + s_part[2][tid] + s_part[3][tid] + ab2[0];
            }
        }
        return;
    }

    #pragma unroll
    for (int mt = 0; mt < 2; mt++) {
        int row0 = rowBase + warp_m * 32 + mt * 16 + g;
        #pragma unroll
        for (int j = 0; j < 8; j++) {
            int lc = warp_n * 64 + j * 8 + cp;
            float bz0 = s_bias[lc], bz1 = s_bias[lc + 1];
            #pragma unroll
            for (int hrow = 0; hrow < 2; hrow++) {
                int row = row0 + hrow * 8;
                if (row >= nRows) continue;
                float v0 = acc[mt][j][hrow * 2]     + bz0;
                float v1 = acc[mt][j][hrow * 2 + 1] + bz1;
                size_t o = (size_t)row * DIM + lc;
                if (MODE == MODE_SPLIT) {
                    v0 = silu_f(v0); v1 = silu_f(v1);
                    uint16_t h0, l0, h1, l1;
                    split1(v0, h0, l0); split1(v1, h1, l1);
                    *(uint32_t*)(Chi + o) = (uint32_t)h0 | ((uint32_t)h1 << 16);
                    *(uint32_t*)(Clo + o) = (uint32_t)l0 | ((uint32_t)l1 << 16);
                } else {
                    *(float2*)(Cf + o) = make_float2(v0, v1);
                }
            }
        }
    }
}

// ---------------- segment softmax readout ----------------------------------
__device__ __forceinline__ int lower_bound_i(const int* __restrict__ a, int n, int v) {
    int lo = 0, hi = n;
    while (lo < hi) { int m = (lo + hi) >> 1; if (a[m] < v) lo = m + 1; else hi = m; }
    return lo;
}

__global__ __launch_bounds__(256) void readout_kernel(
    const float* __restrict__ x, const float* __restrict__ logits,
    const int* __restrict__ batch, float* __restrict__ out, int nRows)
{
    const int g = blockIdx.x, t = threadIdx.x;
    __shared__ float red[256];
    __shared__ float w[256];
    __shared__ int   srange[2];

    if (t == 0) srange[0] = lower_bound_i(batch, nRows, g);
    if (t == 1) srange[1] = lower_bound_i(batch, nRows, g + 1);
    __syncthreads();
    const int start = srange[0], end = srange[1];
    if (start >= end) { out[(size_t)g * DIM + t] = 0.f; return; }

    float m = -3.402823466e38f;
    for (int i = start + t; i < end; i += 256) m = fmaxf(m, logits[i]);
    red[t] = m; __syncthreads();
    #pragma unroll
    for (int s = 128; s; s >>= 1) { if (t < s) red[t] = fmaxf(red[t], red[t+s]); __syncthreads(); }
    m = red[0]; __syncthreads();

    float ssum = 0.f;
    for (int i = start + t; i < end; i += 256) ssum += __expf(logits[i] - m);
    red[t] = ssum; __syncthreads();
    #pragma unroll
    for (int s = 128; s; s >>= 1) { if (t < s) red[t] += red[t+s]; __syncthreads(); }
    const float inv = 1.0f / red[0];
    __syncthreads();

    float acc = 0.f;
    for (int c0 = start; c0 < end; c0 += 256) {
        int i = c0 + t;
        __syncthreads();
        w[t] = (i < end) ? __expf(logits[i] - m) * inv : 0.f;
        __syncthreads();
        int cnt = min(256, end - c0);
        const float* xb = x + (size_t)c0 * DIM + t;
        int j = 0;
        for (; j + 3 < cnt; j += 4) {
            acc += w[j]     * xb[(size_t)j * DIM]
                 + w[j + 1] * xb[(size_t)(j + 1) * DIM]
                 + w[j + 2] * xb[(size_t)(j + 2) * DIM]
                 + w[j + 3] * xb[(size_t)(j + 3) * DIM];
        }
        for (; j < cnt; j++) acc += w[j] * xb[(size_t)j * DIM];
    }
    out[(size_t)g * DIM + t] = acc;
}

// ---------------- launch ----------------------------------------------------
extern "C" void kernel_launch(void* const* d_in, const int* in_sizes, int n_in,
                              void* d_out, int out_size)
{
    const float* X     = (const float*)d_in[0];
    const int*   batch = (const int*)d_in[1];
    const float* W1  = (const float*)d_in[3];
    const float* b1  = (const float*)d_in[4];
    const float* W2  = (const float*)d_in[5];
    const float* b2  = (const float*)d_in[6];
    const float* W3  = (const float*)d_in[7];
    const float* b3  = (const float*)d_in[8];
    const float* aW1 = (const float*)d_in[9];
    const float* ab1 = (const float*)d_in[10];
    const float* aW2 = (const float*)d_in[11];
    const float* ab2 = (const float*)d_in[12];
    float* out = (float*)d_out;

    const int N = in_sizes[0] / DIM;
    const int G = out_size / DIM;

    __nv_bfloat16 *Xhi, *Xlo, *Ahi, *Alo, *Bhi, *Blo, *Wt;
    float *fbuf, *logits;
    cudaGetSymbolAddress((void**)&Xhi, g_Xhi);
    cudaGetSymbolAddress((void**)&Xlo, g_Xlo);
    cudaGetSymbolAddress((void**)&Ahi, g_Ahi);
    cudaGetSymbolAddress((void**)&Alo, g_Alo);
    cudaGetSymbolAddress((void**)&Bhi, g_Bhi);
    cudaGetSymbolAddress((void**)&Blo, g_Blo);
    cudaGetSymbolAddress((void**)&Wt,  g_Wt);
    cudaGetSymbolAddress((void**)&fbuf, g_f);
    cudaGetSymbolAddress((void**)&logits, g_logits);

    __nv_bfloat16* W1h = Wt + 0 * DIM * DIM; __nv_bfloat16* W1l = Wt + 1 * DIM * DIM;
    __nv_bfloat16* W2h = Wt + 2 * DIM * DIM; __nv_bfloat16* W2l = Wt + 3 * DIM * DIM;
    __nv_bfloat16* W3h = Wt + 4 * DIM * DIM; __nv_bfloat16* W3l = Wt + 5 * DIM * DIM;
    __nv_bfloat16* WAh = Wt + 6 * DIM * DIM; __nv_bfloat16* WAl = Wt + 7 * DIM * DIM;

    cudaFuncSetAttribute(gemm_mma<MODE_SPLIT>, cudaFuncAttributeMaxDynamicSharedMemorySize, DYN_SMEM);
    cudaFuncSetAttribute(gemm_mma<MODE_F32>,   cudaFuncAttributeMaxDynamicSharedMemorySize, DYN_SMEM);
    cudaFuncSetAttribute(gemm_mma<MODE_ATT>,   cudaFuncAttributeMaxDynamicSharedMemorySize, DYN_SMEM);

    // prep: split X; transpose+split all weights in one launch
    int n4 = N * (DIM / 4);
    xsplit_kernel<<<(n4 + 255) / 256, 256>>>((const float4*)X, (uint2*)Xhi, (uint2*)Xlo, n4);
    wsplit_all_kernel<<<dim3(DIM, 4), DIM>>>(W1, W2, W3, aW1, Wt);

    const int tiles = (N + BM - 1) / BM;

    // attention branch: logits fused into GEMM epilogue (no intermediate write)
    gemm_mma<MODE_ATT><<<tiles, 512, DYN_SMEM>>>(Xhi, Xlo, WAh, WAl, ab1,
                                                 nullptr, nullptr, nullptr,
                                                 aW2, ab2, logits, N);
    // MLP trunk
    gemm_mma<MODE_SPLIT><<<tiles, 512, DYN_SMEM>>>(Xhi, Xlo, W1h, W1l, b1,
                                                   nullptr, Ahi, Alo,
                                                   nullptr, nullptr, nullptr, N);
    gemm_mma<MODE_SPLIT><<<tiles, 512, DYN_SMEM>>>(Ahi, Alo, W2h, W2l, b2,
                                                   nullptr, Bhi, Blo,
                                                   nullptr, nullptr, nullptr, N);
    gemm_mma<MODE_F32><<<tiles, 512, DYN_SMEM>>>(Bhi, Blo, W3h, W3l, b3,
                                                 fbuf, nullptr, nullptr,
                                                 nullptr, nullptr, nullptr, N);

    // softmax readout
    readout_kernel<<<G, 256>>>(fbuf, logits, batch, out, N);
}

// round 6
// speedup vs baseline: 1.2428x; 1.2428x over previous
#include <cuda_runtime.h>
#include <cuda_bf16.h>
#include <cstdint>
#include <cstddef>

// ===========================================================================
// InvariantReadout — bf16-split mma.sync (HMMA), round 6
//   Weights (B) fully SMEM-resident; A streamed via 2-stage 32KB buffer.
//   h1 = silu(X@W1+b1); h2 = silu(h1@W2+b2); x = h2@W3+b3
//   logits = silu(X@aW1+ab1)@aW2 + ab2 (fused, per-col-half partials)
//   per-segment softmax -> weighted segment sum -> (G, 256)
// fp32 split to bf16 hi/lo; D = Ahi*Bhi + Ahi*Blo + Alo*Bhi (err ~2^-16).
// R5 bug fixed: MODE_ATT partials now indexed by blockIdx.y (col half).
// ===========================================================================

#define NMAX 200000
#define DIM  256
#define BM   128
#define BN   128
#define BKT  64                       // A k-elems per stage
#define KTILES (DIM / BKT)            // 4
// SMEM map (dynamic):
//   B resident: Bhi [128n x 256k] 64KB, Blo 64KB             -> 128KB
//   A stages  : 2 x (Ahi 16KB + Alo 16KB)                    ->  64KB
#define OFF_B    0
#define B_HALF   65536
#define OFF_AST  131072
#define A_STAGE  32768
#define A_HALF   16384
#define DYN_SMEM 196608

#define MODE_SPLIT 0   // silu + split -> bf16 hi/lo
#define MODE_F32   1   // bias only -> fp32
#define MODE_ATT   2   // silu, dot aW2 -> per-col-half partial logits

// ---------------- scratch ---------------------------------------------------
__device__ __nv_bfloat16 g_Xhi[(size_t)NMAX * DIM];
__device__ __nv_bfloat16 g_Xlo[(size_t)NMAX * DIM];
__device__ __nv_bfloat16 g_Ahi[(size_t)NMAX * DIM];
__device__ __nv_bfloat16 g_Alo[(size_t)NMAX * DIM];
__device__ __nv_bfloat16 g_Bhi[(size_t)NMAX * DIM];
__device__ __nv_bfloat16 g_Blo[(size_t)NMAX * DIM];
__device__ float         g_f[(size_t)NMAX * DIM];   // fp32 x
__device__ float         g_att[2][NMAX];            // per-col-half logit partials
__device__ float         g_logits[NMAX];
__device__ __nv_bfloat16 g_Wt[8][DIM * DIM];        // {W1,W2,W3,aW1} x {hi,lo}, n-major

// ---------------- helpers ---------------------------------------------------
__device__ __forceinline__ uint32_t smem_u32(const void* p) {
    uint32_t a;
    asm("{ .reg .u64 t; cvta.to.shared.u64 t, %1; cvt.u32.u64 %0, t; }" : "=r"(a) : "l"(p));
    return a;
}
__device__ __forceinline__ void cp16(uint32_t dst, const void* src) {
    asm volatile("cp.async.cg.shared.global [%0], [%1], 16;" :: "r"(dst), "l"(src) : "memory");
}
__device__ __forceinline__ void cp_commit() {
    asm volatile("cp.async.commit_group;" ::: "memory");
}
template <int NW>
__device__ __forceinline__ void cp_wait() {
    asm volatile("cp.async.wait_group %0;" :: "n"(NW) : "memory");
}
__device__ __forceinline__ void ldsm4(uint32_t* r, uint32_t addr) {
    asm volatile("ldmatrix.sync.aligned.m8n8.x4.shared.b16 {%0,%1,%2,%3}, [%4];"
                 : "=r"(r[0]), "=r"(r[1]), "=r"(r[2]), "=r"(r[3]) : "r"(addr));
}
__device__ __forceinline__ void mma16816(float* d, const uint32_t* a, const uint32_t* b) {
    asm volatile(
        "mma.sync.aligned.m16n8k16.row.col.f32.bf16.bf16.f32 "
        "{%0,%1,%2,%3}, {%4,%5,%6,%7}, {%8,%9}, {%0,%1,%2,%3};"
        : "+f"(d[0]), "+f"(d[1]), "+f"(d[2]), "+f"(d[3])
        : "r"(a[0]), "r"(a[1]), "r"(a[2]), "r"(a[3]), "r"(b[0]), "r"(b[1]));
}
__device__ __forceinline__ float silu_f(float x) { return x / (1.0f + __expf(-x)); }
__device__ __forceinline__ void split1(float v, uint16_t& h, uint16_t& l) {
    __nv_bfloat16 hb = __float2bfloat16(v);
    float hf = __bfloat162float(hb);
    __nv_bfloat16 lb = __float2bfloat16(v - hf);
    h = __bfloat16_as_ushort(hb);
    l = __bfloat16_as_ushort(lb);
}

// ---------------- prep kernels ---------------------------------------------
__global__ __launch_bounds__(256) void xsplit_kernel(
    const float4* __restrict__ X, uint2* __restrict__ hi, uint2* __restrict__ lo, int n4)
{
    int i = blockIdx.x * 256 + threadIdx.x;
    if (i >= n4) return;
    float4 v = X[i];
    uint16_t h0,l0,h1,l1,h2,l2,h3,l3;
    split1(v.x,h0,l0); split1(v.y,h1,l1); split1(v.z,h2,l2); split1(v.w,h3,l3);
    hi[i] = make_uint2((uint32_t)h0 | ((uint32_t)h1<<16), (uint32_t)h2 | ((uint32_t)h3<<16));
    lo[i] = make_uint2((uint32_t)l0 | ((uint32_t)l1<<16), (uint32_t)l2 | ((uint32_t)l3<<16));
}

__global__ __launch_bounds__(256) void wsplit_all_kernel(
    const float* __restrict__ W1, const float* __restrict__ W2,
    const float* __restrict__ W3, const float* __restrict__ WA,
    __nv_bfloat16* __restrict__ Wt)
{
    int n = blockIdx.x, k = threadIdx.x, w = blockIdx.y;
    const float* W = (w == 0) ? W1 : (w == 1) ? W2 : (w == 2) ? W3 : WA;
    float v = W[k * DIM + n];
    uint16_t h, l; split1(v, h, l);
    Wt[(size_t)(2 * w)     * DIM * DIM + n * DIM + k] = __ushort_as_bfloat16(h);
    Wt[(size_t)(2 * w + 1) * DIM * DIM + n * DIM + k] = __ushort_as_bfloat16(l);
}

// combine attention partials -> logits
__global__ __launch_bounds__(256) void att_combine_kernel(
    const float* __restrict__ p0, const float* __restrict__ p1,
    const float* __restrict__ ab2, float* __restrict__ logits, int n)
{
    int i = blockIdx.x * 256 + threadIdx.x;
    if (i < n) logits[i] = p0[i] + p1[i] + ab2[0];
}

// ---------------- mma.sync GEMM ---------------------------------------------
// B (weights, n-major [n][k]) resident in SMEM for all K; A double-buffered.
template <int MODE>
__global__ __launch_bounds__(256) void gemm_mma(
    const __nv_bfloat16* __restrict__ Ahi, const __nv_bfloat16* __restrict__ Alo,
    const __nv_bfloat16* __restrict__ Bhi, const __nv_bfloat16* __restrict__ Blo,
    const float* __restrict__ bias,
    float* __restrict__ Cf, __nv_bfloat16* __restrict__ Chi, __nv_bfloat16* __restrict__ Clo,
    const float* __restrict__ aW2, float* __restrict__ attp, int nRows)
{
    extern __shared__ char sm[];
    __shared__ float s_bias[BN];
    __shared__ float s_aw2[BN];
    __shared__ float s_part[2][BM];

    const int tid  = threadIdx.x;
    const int wid  = tid >> 5;
    const int lane = tid & 31;
    const int warp_m = wid >> 1;        // 0..3 -> 32-row slab
    const int warp_n = wid & 1;         // 0..1 -> 64-col slab
    const int rowBase = blockIdx.x * BM;
    const int colBase = blockIdx.y * BN;

    if (tid < BN) {
        s_bias[tid] = bias[colBase + tid];
        if (MODE == MODE_ATT) s_aw2[tid] = aW2[colBase + tid];
    }

    const uint32_t smb = smem_u32(sm);

    // ---- load resident B: 128 n-rows x 32 chunks(16B) per half, swizzled ----
    {
        const __nv_bfloat16* bh = Bhi + (size_t)colBase * DIM;
        const __nv_bfloat16* bl = Blo + (size_t)colBase * DIM;
        #pragma unroll
        for (int i = 0; i < 16; i++) {
            int f = tid + i * 256;
            int r = f >> 5, c = f & 31;                     // n-row, 16B chunk
            uint32_t p = (uint32_t)((c & 24) | ((c ^ r) & 7));
            uint32_t off = (uint32_t)(r * 512) + p * 16;
            size_t go = (size_t)r * DIM + c * 8;
            cp16(smb + OFF_B + off,          bh + go);
            cp16(smb + OFF_B + B_HALF + off, bl + go);
        }
    }
    // ---- A stage loader: 128 rows x 8 chunks(16B), hi+lo ----
    auto load_A = [&](int s, int kt) {
        const uint32_t st = smb + OFF_AST + s * A_STAGE;
        const int ke = kt * BKT;
        #pragma unroll
        for (int i = 0; i < 4; i++) {
            int f = tid + i * 256;
            int r = f >> 3, c = f & 7;
            uint32_t off = (uint32_t)(r * 128 + ((c ^ (r & 7)) << 4));
            int gr = rowBase + r; if (gr >= nRows) gr = nRows - 1;
            size_t ga = (size_t)gr * DIM + ke + c * 8;
            cp16(st + off,          Ahi + ga);
            cp16(st + A_HALF + off, Alo + ga);
        }
        cp_commit();
    };

    load_A(0, 0);       // group: B + A0
    load_A(1, 1);       // group: A1

    float acc[2][8][4];
    #pragma unroll
    for (int mt = 0; mt < 2; mt++)
        #pragma unroll
        for (int j = 0; j < 8; j++)
            #pragma unroll
            for (int q = 0; q < 4; q++) acc[mt][j][q] = 0.f;

    const int rrA = (lane & 7) + ((lane >> 3) & 1) * 8;
    const int khA = lane >> 4;
    const int rrB = (lane & 7) + (lane >> 4) * 8;
    const int khB = (lane >> 3) & 1;

    for (int kt = 0; kt < KTILES; kt++) {
        cp_wait<1>();            // stage kt (and B on first iter) complete
        __syncthreads();

        const uint32_t ast = smb + OFF_AST + (kt & 1) * A_STAGE;

        #pragma unroll
        for (int ks = 0; ks < 4; ks++) {
            uint32_t ah[2][4], al[2][4];
            #pragma unroll
            for (int mt = 0; mt < 2; mt++) {
                int row = warp_m * 32 + mt * 16 + rrA;
                uint32_t a = ast + row * 128 + (((ks * 2 + khA) ^ (row & 7)) << 4);
                ldsm4(ah[mt], a);
                ldsm4(al[mt], a + A_HALF);
            }
            const int cB = (kt * 4 + ks) * 2 + khB;          // 16B chunk in full K
            #pragma unroll
            for (int nt = 0; nt < 4; nt++) {
                int row = warp_n * 64 + nt * 16 + rrB;
                uint32_t p = (uint32_t)((cB & 24) | ((cB ^ row) & 7));
                uint32_t b = smb + OFF_B + row * 512 + p * 16;
                uint32_t bh[4], bl[4];
                ldsm4(bh, b);
                ldsm4(bl, b + B_HALF);
                #pragma unroll
                for (int mt = 0; mt < 2; mt++)
                    #pragma unroll
                    for (int h = 0; h < 2; h++) {
                        float* d = acc[mt][nt * 2 + h];
                        mma16816(d, ah[mt], &bh[h * 2]);     // hi*hi
                        mma16816(d, ah[mt], &bl[h * 2]);     // hi*lo
                        mma16816(d, al[mt], &bh[h * 2]);     // lo*hi
                    }
            }
        }
        __syncthreads();                          // all warps done with stage kt
        if (kt + 2 < KTILES) load_A(kt & 1, kt + 2);
        else cp_commit();                         // keep group count in step
    }

    // ---- epilogue ----
    const int g  = lane >> 2;
    const int cp = (lane & 3) * 2;

    if (MODE == MODE_ATT) {
        float part[2][2] = {{0.f, 0.f}, {0.f, 0.f}};
        #pragma unroll
        for (int mt = 0; mt < 2; mt++)
            #pragma unroll
            for (int j = 0; j < 8; j++) {
                int lc = warp_n * 64 + j * 8 + cp;
                float bz0 = s_bias[lc], bz1 = s_bias[lc + 1];
                float w0 = s_aw2[lc],  w1 = s_aw2[lc + 1];
                #pragma unroll
                for (int hrow = 0; hrow < 2; hrow++) {
                    float v0 = silu_f(acc[mt][j][hrow * 2]     + bz0);
                    float v1 = silu_f(acc[mt][j][hrow * 2 + 1] + bz1);
                    part[mt][hrow] += v0 * w0 + v1 * w1;
                }
            }
        #pragma unroll
        for (int mt = 0; mt < 2; mt++)
            #pragma unroll
            for (int hrow = 0; hrow < 2; hrow++) {
                float p = part[mt][hrow];
                p += __shfl_xor_sync(0xFFFFFFFFu, p, 1);
                p += __shfl_xor_sync(0xFFFFFFFFu, p, 2);
                if ((lane & 3) == 0)
                    s_part[warp_n][warp_m * 32 + mt * 16 + hrow * 8 + g] = p;
            }
        __syncthreads();
        if (tid < BM) {
            int row = rowBase + tid;
            if (row < nRows)
                attp[(size_t)blockIdx.y * NMAX + row] =       // FIX: per-half slot
                    s_part[0][tid] + s_part[1][tid];
        }
        return;
    }

    #pragma unroll
    for (int mt = 0; mt < 2; mt++) {
        int row0 = rowBase + warp_m * 32 + mt * 16 + g;
        #pragma unroll
        for (int j = 0; j < 8; j++) {
            int lc = warp_n * 64 + j * 8 + cp;
            float bz0 = s_bias[lc], bz1 = s_bias[lc + 1];
            #pragma unroll
            for (int hrow = 0; hrow < 2; hrow++) {
                int row = row0 + hrow * 8;
                if (row >= nRows) continue;
                float v0 = acc[mt][j][hrow * 2]     + bz0;
                float v1 = acc[mt][j][hrow * 2 + 1] + bz1;
                size_t o = (size_t)row * DIM + colBase + lc;
                if (MODE == MODE_SPLIT) {
                    v0 = silu_f(v0); v1 = silu_f(v1);
                    uint16_t h0, l0, h1, l1;
                    split1(v0, h0, l0); split1(v1, h1, l1);
                    *(uint32_t*)(Chi + o) = (uint32_t)h0 | ((uint32_t)h1 << 16);
                    *(uint32_t*)(Clo + o) = (uint32_t)l0 | ((uint32_t)l1 << 16);
                } else {
                    *(float2*)(Cf + o) = make_float2(v0, v1);
                }
            }
        }
    }
}

// ---------------- segment softmax readout ----------------------------------
__device__ __forceinline__ int lower_bound_i(const int* __restrict__ a, int n, int v) {
    int lo = 0, hi = n;
    while (lo < hi) { int m = (lo + hi) >> 1; if (a[m] < v) lo = m + 1; else hi = m; }
    return lo;
}

__global__ __launch_bounds__(256) void readout_kernel(
    const float* __restrict__ x, const float* __restrict__ logits,
    const int* __restrict__ batch, float* __restrict__ out, int nRows)
{
    const int g = blockIdx.x, t = threadIdx.x;
    __shared__ float red[256];
    __shared__ float w[256];
    __shared__ int   srange[2];

    if (t == 0) srange[0] = lower_bound_i(batch, nRows, g);
    if (t == 1) srange[1] = lower_bound_i(batch, nRows, g + 1);
    __syncthreads();
    const int start = srange[0], end = srange[1];
    if (start >= end) { out[(size_t)g * DIM + t] = 0.f; return; }

    float m = -3.402823466e38f;
    for (int i = start + t; i < end; i += 256) m = fmaxf(m, logits[i]);
    red[t] = m; __syncthreads();
    #pragma unroll
    for (int s = 128; s; s >>= 1) { if (t < s) red[t] = fmaxf(red[t], red[t+s]); __syncthreads(); }
    m = red[0]; __syncthreads();

    float ssum = 0.f;
    for (int i = start + t; i < end; i += 256) ssum += __expf(logits[i] - m);
    red[t] = ssum; __syncthreads();
    #pragma unroll
    for (int s = 128; s; s >>= 1) { if (t < s) red[t] += red[t+s]; __syncthreads(); }
    const float inv = 1.0f / red[0];
    __syncthreads();

    float acc = 0.f;
    for (int c0 = start; c0 < end; c0 += 256) {
        int i = c0 + t;
        __syncthreads();
        w[t] = (i < end) ? __expf(logits[i] - m) * inv : 0.f;
        __syncthreads();
        int cnt = min(256, end - c0);
        const float* xb = x + (size_t)c0 * DIM + t;
        int j = 0;
        for (; j + 3 < cnt; j += 4) {
            acc += w[j]     * xb[(size_t)j * DIM]
                 + w[j + 1] * xb[(size_t)(j + 1) * DIM]
                 + w[j + 2] * xb[(size_t)(j + 2) * DIM]
                 + w[j + 3] * xb[(size_t)(j + 3) * DIM];
        }
        for (; j < cnt; j++) acc += w[j] * xb[(size_t)j * DIM];
    }
    out[(size_t)g * DIM + t] = acc;
}

// ---------------- launch ----------------------------------------------------
extern "C" void kernel_launch(void* const* d_in, const int* in_sizes, int n_in,
                              void* d_out, int out_size)
{
    const float* X     = (const float*)d_in[0];
    const int*   batch = (const int*)d_in[1];
    const float* W1  = (const float*)d_in[3];
    const float* b1  = (const float*)d_in[4];
    const float* W2  = (const float*)d_in[5];
    const float* b2  = (const float*)d_in[6];
    const float* W3  = (const float*)d_in[7];
    const float* b3  = (const float*)d_in[8];
    const float* aW1 = (const float*)d_in[9];
    const float* ab1 = (const float*)d_in[10];
    const float* aW2 = (const float*)d_in[11];
    const float* ab2 = (const float*)d_in[12];
    float* out = (float*)d_out;

    const int N = in_sizes[0] / DIM;
    const int G = out_size / DIM;

    __nv_bfloat16 *Xhi, *Xlo, *Ahi, *Alo, *Bhi, *Blo, *Wt;
    float *fbuf, *logits, *att;
    cudaGetSymbolAddress((void**)&Xhi, g_Xhi);
    cudaGetSymbolAddress((void**)&Xlo, g_Xlo);
    cudaGetSymbolAddress((void**)&Ahi, g_Ahi);
    cudaGetSymbolAddress((void**)&Alo, g_Alo);
    cudaGetSymbolAddress((void**)&Bhi, g_Bhi);
    cudaGetSymbolAddress((void**)&Blo, g_Blo);
    cudaGetSymbolAddress((void**)&Wt,  g_Wt);
    cudaGetSymbolAddress((void**)&fbuf, g_f);
    cudaGetSymbolAddress((void**)&logits, g_logits);
    cudaGetSymbolAddress((void**)&att, g_att);

    __nv_bfloat16* W1h = Wt + 0 * DIM * DIM; __nv_bfloat16* W1l = Wt + 1 * DIM * DIM;
    __nv_bfloat16* W2h = Wt + 2 * DIM * DIM; __nv_bfloat16* W2l = Wt + 3 * DIM * DIM;
    __nv_bfloat16* W3h = Wt + 4 * DIM * DIM; __nv_bfloat16* W3l = Wt + 5 * DIM * DIM;
    __nv_bfloat16* WAh = Wt + 6 * DIM * DIM; __nv_bfloat16* WAl = Wt + 7 * DIM * DIM;

    cudaFuncSetAttribute(gemm_mma<MODE_SPLIT>, cudaFuncAttributeMaxDynamicSharedMemorySize, DYN_SMEM);
    cudaFuncSetAttribute(gemm_mma<MODE_F32>,   cudaFuncAttributeMaxDynamicSharedMemorySize, DYN_SMEM);
    cudaFuncSetAttribute(gemm_mma<MODE_ATT>,   cudaFuncAttributeMaxDynamicSharedMemorySize, DYN_SMEM);

    int n4 = N * (DIM / 4);
    xsplit_kernel<<<(n4 + 255) / 256, 256>>>((const float4*)X, (uint2*)Xhi, (uint2*)Xlo, n4);
    wsplit_all_kernel<<<dim3(DIM, 4), DIM>>>(W1, W2, W3, aW1, Wt);

    const int tiles = (N + BM - 1) / BM;
    dim3 grid(tiles, 2);

    // attention branch (partials per col-half, then combine)
    gemm_mma<MODE_ATT><<<grid, 256, DYN_SMEM>>>(Xhi, Xlo, WAh, WAl, ab1,
                                                nullptr, nullptr, nullptr,
                                                aW2, att, N);
    att_combine_kernel<<<(N + 255) / 256, 256>>>(att, att + NMAX, ab2, logits, N);

    // MLP trunk
    gemm_mma<MODE_SPLIT><<<grid, 256, DYN_SMEM>>>(Xhi, Xlo, W1h, W1l, b1,
                                                  nullptr, Ahi, Alo,
                                                  nullptr, nullptr, N);
    gemm_mma<MODE_SPLIT><<<grid, 256, DYN_SMEM>>>(Ahi, Alo, W2h, W2l, b2,
                                                  nullptr, Bhi, Blo,
                                                  nullptr, nullptr, N);
    gemm_mma<MODE_F32><<<grid, 256, DYN_SMEM>>>(Bhi, Blo, W3h, W3l, b3,
                                                fbuf, nullptr, nullptr,
                                                nullptr, nullptr, N);

    // softmax readout
    readout_kernel<<<G, 256>>>(fbuf, logits, batch, out, N);
}

// round 7
// speedup vs baseline: 1.5426x; 1.2412x over previous
#include <cuda_runtime.h>
#include <cuda_bf16.h>
#include <cstdint>
#include <cstddef>

// ===========================================================================
// InvariantReadout — bf16-split mma.sync (HMMA), round 7
//   2 CTAs/SM: BK=32, hi/lo packed per 128B row, 3-stage ring, 96KB smem.
//   h1 = silu(X@W1+b1); h2 = silu(h1@W2+b2); x = h2@W3+b3
//   logits = silu(X@aW1+ab1)@aW2 + ab2 (fused, per-col-half partials)
//   per-segment softmax -> weighted segment sum -> (G, 256)
// fp32 split to bf16 hi/lo; D = Ahi*Bhi + Ahi*Blo + Alo*Bhi (err ~2^-16).
// ===========================================================================

#define NMAX 200000
#define DIM  256
#define BM   128
#define BN   128
#define BKT  32                       // k-elems per stage
#define KTILES (DIM / BKT)            // 8
// Stage layout: A tile 128 rows x 128B (32k hi | 32k lo), B tile same.
#define A_TILE   16384
#define STAGE    32768                // A + B
#define NSTAGE   3
#define DYN_SMEM (NSTAGE * STAGE)     // 96 KB

#define MODE_SPLIT 0   // silu + split -> bf16 hi/lo
#define MODE_F32   1   // bias only -> fp32
#define MODE_ATT   2   // silu, dot aW2 -> per-col-half partial logits

// ---------------- scratch ---------------------------------------------------
__device__ __nv_bfloat16 g_Xhi[(size_t)NMAX * DIM];
__device__ __nv_bfloat16 g_Xlo[(size_t)NMAX * DIM];
__device__ __nv_bfloat16 g_Ahi[(size_t)NMAX * DIM];
__device__ __nv_bfloat16 g_Alo[(size_t)NMAX * DIM];
__device__ __nv_bfloat16 g_Bhi[(size_t)NMAX * DIM];
__device__ __nv_bfloat16 g_Blo[(size_t)NMAX * DIM];
__device__ float         g_f[(size_t)NMAX * DIM];   // fp32 x
__device__ float         g_att[2][NMAX];            // per-col-half logit partials
__device__ float         g_logits[NMAX];
__device__ __nv_bfloat16 g_Wt[8][DIM * DIM];        // {W1,W2,W3,aW1} x {hi,lo}, n-major

// ---------------- helpers ---------------------------------------------------
__device__ __forceinline__ uint32_t smem_u32(const void* p) {
    uint32_t a;
    asm("{ .reg .u64 t; cvta.to.shared.u64 t, %1; cvt.u32.u64 %0, t; }" : "=r"(a) : "l"(p));
    return a;
}
__device__ __forceinline__ void cp16(uint32_t dst, const void* src) {
    asm volatile("cp.async.cg.shared.global [%0], [%1], 16;" :: "r"(dst), "l"(src) : "memory");
}
__device__ __forceinline__ void cp_commit() {
    asm volatile("cp.async.commit_group;" ::: "memory");
}
template <int NW>
__device__ __forceinline__ void cp_wait() {
    asm volatile("cp.async.wait_group %0;" :: "n"(NW) : "memory");
}
__device__ __forceinline__ void ldsm4(uint32_t* r, uint32_t addr) {
    asm volatile("ldmatrix.sync.aligned.m8n8.x4.shared.b16 {%0,%1,%2,%3}, [%4];"
                 : "=r"(r[0]), "=r"(r[1]), "=r"(r[2]), "=r"(r[3]) : "r"(addr));
}
__device__ __forceinline__ void mma16816(float* d, const uint32_t* a, const uint32_t* b) {
    asm volatile(
        "mma.sync.aligned.m16n8k16.row.col.f32.bf16.bf16.f32 "
        "{%0,%1,%2,%3}, {%4,%5,%6,%7}, {%8,%9}, {%0,%1,%2,%3};"
        : "+f"(d[0]), "+f"(d[1]), "+f"(d[2]), "+f"(d[3])
        : "r"(a[0]), "r"(a[1]), "r"(a[2]), "r"(a[3]), "r"(b[0]), "r"(b[1]));
}
__device__ __forceinline__ float silu_f(float x) { return x / (1.0f + __expf(-x)); }
__device__ __forceinline__ void split1(float v, uint16_t& h, uint16_t& l) {
    __nv_bfloat16 hb = __float2bfloat16(v);
    float hf = __bfloat162float(hb);
    __nv_bfloat16 lb = __float2bfloat16(v - hf);
    h = __bfloat16_as_ushort(hb);
    l = __bfloat16_as_ushort(lb);
}

// ---------------- prep kernels ---------------------------------------------
__global__ __launch_bounds__(256) void xsplit_kernel(
    const float4* __restrict__ X, uint2* __restrict__ hi, uint2* __restrict__ lo, int n4)
{
    int i = blockIdx.x * 256 + threadIdx.x;
    if (i >= n4) return;
    float4 v = X[i];
    uint16_t h0,l0,h1,l1,h2,l2,h3,l3;
    split1(v.x,h0,l0); split1(v.y,h1,l1); split1(v.z,h2,l2); split1(v.w,h3,l3);
    hi[i] = make_uint2((uint32_t)h0 | ((uint32_t)h1<<16), (uint32_t)h2 | ((uint32_t)h3<<16));
    lo[i] = make_uint2((uint32_t)l0 | ((uint32_t)l1<<16), (uint32_t)l2 | ((uint32_t)l3<<16));
}

__global__ __launch_bounds__(256) void wsplit_all_kernel(
    const float* __restrict__ W1, const float* __restrict__ W2,
    const float* __restrict__ W3, const float* __restrict__ WA,
    __nv_bfloat16* __restrict__ Wt)
{
    int n = blockIdx.x, k = threadIdx.x, w = blockIdx.y;
    const float* W = (w == 0) ? W1 : (w == 1) ? W2 : (w == 2) ? W3 : WA;
    float v = W[k * DIM + n];
    uint16_t h, l; split1(v, h, l);
    Wt[(size_t)(2 * w)     * DIM * DIM + n * DIM + k] = __ushort_as_bfloat16(h);
    Wt[(size_t)(2 * w + 1) * DIM * DIM + n * DIM + k] = __ushort_as_bfloat16(l);
}

// combine attention partials -> logits
__global__ __launch_bounds__(256) void att_combine_kernel(
    const float* __restrict__ p0, const float* __restrict__ p1,
    const float* __restrict__ ab2, float* __restrict__ logits, int n)
{
    int i = blockIdx.x * 256 + threadIdx.x;
    if (i < n) logits[i] = p0[i] + p1[i] + ab2[0];
}

// ---------------- mma.sync GEMM ---------------------------------------------
// Both operands streamed; stage row = [32k hi | 32k lo], SW128 swizzle.
template <int MODE>
__global__ __launch_bounds__(256, 2) void gemm_mma(
    const __nv_bfloat16* __restrict__ Ahi, const __nv_bfloat16* __restrict__ Alo,
    const __nv_bfloat16* __restrict__ Bhi, const __nv_bfloat16* __restrict__ Blo,
    const float* __restrict__ bias,
    float* __restrict__ Cf, __nv_bfloat16* __restrict__ Chi, __nv_bfloat16* __restrict__ Clo,
    const float* __restrict__ aW2, float* __restrict__ attp, int nRows)
{
    extern __shared__ char sm[];
    __shared__ float s_bias[BN];
    __shared__ float s_aw2[BN];
    __shared__ float s_part[2][BM];

    const int tid  = threadIdx.x;
    const int wid  = tid >> 5;
    const int lane = tid & 31;
    const int warp_m = wid >> 1;        // 0..3 -> 32-row slab
    const int warp_n = wid & 1;         // 0..1 -> 64-col slab
    const int rowBase = blockIdx.x * BM;
    const int colBase = blockIdx.y * BN;

    if (tid < BN) {
        s_bias[tid] = bias[colBase + tid];
        if (MODE == MODE_ATT) s_aw2[tid] = aW2[colBase + tid];
    }

    const uint32_t smb = smem_u32(sm);

    // per-thread stage-load geometry (1024 16B chunks per tile, 4/thread)
    const int lr = tid >> 1;                    // row 0..127 (2 thr/row)
    // each thread covers 4 chunks of its row: c = (tid&1)*4 + q? -> use 4 iters
    auto load_stage = [&](int s, int kt) {
        const uint32_t st = smb + s * STAGE;
        const int ke = kt * BKT;
        #pragma unroll
        for (int i = 0; i < 4; i++) {
            int f = tid + i * 256;              // 0..1023
            int r = f >> 3, c = f & 7;          // row, 16B chunk
            uint32_t off = (uint32_t)(r * 128 + ((c ^ (r & 7)) << 4));
            int kk = ke + (c & 3) * 8;
            // A tile
            int gr = rowBase + r; if (gr >= nRows) gr = nRows - 1;
            size_t ga = (size_t)gr * DIM + kk;
            cp16(st + off, (c < 4) ? (const void*)(Ahi + ga) : (const void*)(Alo + ga));
            // B tile
            size_t gb = (size_t)(colBase + r) * DIM + kk;
            cp16(st + A_TILE + off, (c < 4) ? (const void*)(Bhi + gb) : (const void*)(Blo + gb));
        }
        cp_commit();
    };
    (void)lr;

    load_stage(0, 0);
    load_stage(1, 1);

    float acc[2][8][4];
    #pragma unroll
    for (int mt = 0; mt < 2; mt++)
        #pragma unroll
        for (int j = 0; j < 8; j++)
            #pragma unroll
            for (int q = 0; q < 4; q++) acc[mt][j][q] = 0.f;

    const int rrA = (lane & 7) + ((lane >> 3) & 1) * 8;
    const int khA = lane >> 4;
    const int rrB = (lane & 7) + (lane >> 4) * 8;
    const int khB = (lane >> 3) & 1;

    int sbuf = 0;                                 // stage index for kt
    for (int kt = 0; kt < KTILES; kt++) {
        cp_wait<1>();                             // stage kt complete
        __syncthreads();                          // also: all warps done with kt-1
        if (kt + 2 < KTILES) {
            int ns = sbuf + 2; if (ns >= NSTAGE) ns -= NSTAGE;
            load_stage(ns, kt + 2);               // safe: that buf was consumed at kt-1
        } else {
            cp_commit();                          // keep group accounting in step
        }

        const uint32_t ast = smb + sbuf * STAGE;

        #pragma unroll
        for (int ks = 0; ks < 2; ks++) {          // 2 x k16 steps in BK=32
            const int cA = ks * 2 + khA;          // hi chunk 0..3 (lo = +4)
            const int cB = ks * 2 + khB;
            uint32_t ah[2][4], al[2][4];
            #pragma unroll
            for (int mt = 0; mt < 2; mt++) {
                int row = warp_m * 32 + mt * 16 + rrA;
                uint32_t rb = ast + row * 128;
                int r7 = row & 7;
                ldsm4(ah[mt], rb + ((cA       ^ r7) << 4));
                ldsm4(al[mt], rb + (((cA + 4) ^ r7) << 4));
            }
            #pragma unroll
            for (int nt = 0; nt < 4; nt++) {
                int row = warp_n * 64 + nt * 16 + rrB;
                uint32_t rb = ast + A_TILE + row * 128;
                int r7 = row & 7;
                uint32_t bh[4], bl[4];
                ldsm4(bh, rb + ((cB       ^ r7) << 4));
                ldsm4(bl, rb + (((cB + 4) ^ r7) << 4));
                #pragma unroll
                for (int mt = 0; mt < 2; mt++)
                    #pragma unroll
                    for (int h = 0; h < 2; h++) {
                        float* d = acc[mt][nt * 2 + h];
                        mma16816(d, ah[mt], &bh[h * 2]);     // hi*hi
                        mma16816(d, ah[mt], &bl[h * 2]);     // hi*lo
                        mma16816(d, al[mt], &bh[h * 2]);     // lo*hi
                    }
            }
        }
        if (++sbuf >= NSTAGE) sbuf = 0;
    }

    // ---- epilogue ----
    const int g  = lane >> 2;
    const int cp = (lane & 3) * 2;

    if (MODE == MODE_ATT) {
        float part[2][2] = {{0.f, 0.f}, {0.f, 0.f}};
        #pragma unroll
        for (int mt = 0; mt < 2; mt++)
            #pragma unroll
            for (int j = 0; j < 8; j++) {
                int lc = warp_n * 64 + j * 8 + cp;
                float bz0 = s_bias[lc], bz1 = s_bias[lc + 1];
                float w0 = s_aw2[lc],  w1 = s_aw2[lc + 1];
                #pragma unroll
                for (int hrow = 0; hrow < 2; hrow++) {
                    float v0 = silu_f(acc[mt][j][hrow * 2]     + bz0);
                    float v1 = silu_f(acc[mt][j][hrow * 2 + 1] + bz1);
                    part[mt][hrow] += v0 * w0 + v1 * w1;
                }
            }
        #pragma unroll
        for (int mt = 0; mt < 2; mt++)
            #pragma unroll
            for (int hrow = 0; hrow < 2; hrow++) {
                float p = part[mt][hrow];
                p += __shfl_xor_sync(0xFFFFFFFFu, p, 1);
                p += __shfl_xor_sync(0xFFFFFFFFu, p, 2);
                if ((lane & 3) == 0)
                    s_part[warp_n][warp_m * 32 + mt * 16 + hrow * 8 + g] = p;
            }
        __syncthreads();
        if (tid < BM) {
            int row = rowBase + tid;
            if (row < nRows)
                attp[(size_t)blockIdx.y * NMAX + row] =
                    s_part[0][tid] + s_part[1][tid];
        }
        return;
    }

    #pragma unroll
    for (int mt = 0; mt < 2; mt++) {
        int row0 = rowBase + warp_m * 32 + mt * 16 + g;
        #pragma unroll
        for (int j = 0; j < 8; j++) {
            int lc = warp_n * 64 + j * 8 + cp;
            float bz0 = s_bias[lc], bz1 = s_bias[lc + 1];
            #pragma unroll
            for (int hrow = 0; hrow < 2; hrow++) {
                int row = row0 + hrow * 8;
                if (row >= nRows) continue;
                float v0 = acc[mt][j][hrow * 2]     + bz0;
                float v1 = acc[mt][j][hrow * 2 + 1] + bz1;
                size_t o = (size_t)row * DIM + colBase + lc;
                if (MODE == MODE_SPLIT) {
                    v0 = silu_f(v0); v1 = silu_f(v1);
                    uint16_t h0, l0, h1, l1;
                    split1(v0, h0, l0); split1(v1, h1, l1);
                    *(uint32_t*)(Chi + o) = (uint32_t)h0 | ((uint32_t)h1 << 16);
                    *(uint32_t*)(Clo + o) = (uint32_t)l0 | ((uint32_t)l1 << 16);
                } else {
                    *(float2*)(Cf + o) = make_float2(v0, v1);
                }
            }
        }
    }
}

// ---------------- segment softmax readout ----------------------------------
__device__ __forceinline__ int lower_bound_i(const int* __restrict__ a, int n, int v) {
    int lo = 0, hi = n;
    while (lo < hi) { int m = (lo + hi) >> 1; if (a[m] < v) lo = m + 1; else hi = m; }
    return lo;
}

__global__ __launch_bounds__(256) void readout_kernel(
    const float* __restrict__ x, const float* __restrict__ logits,
    const int* __restrict__ batch, float* __restrict__ out, int nRows)
{
    const int g = blockIdx.x, t = threadIdx.x;
    __shared__ float red[256];
    __shared__ float w[256];
    __shared__ int   srange[2];

    if (t == 0) srange[0] = lower_bound_i(batch, nRows, g);
    if (t == 1) srange[1] = lower_bound_i(batch, nRows, g + 1);
    __syncthreads();
    const int start = srange[0], end = srange[1];
    if (start >= end) { out[(size_t)g * DIM + t] = 0.f; return; }

    float m = -3.402823466e38f;
    for (int i = start + t; i < end; i += 256) m = fmaxf(m, logits[i]);
    red[t] = m; __syncthreads();
    #pragma unroll
    for (int s = 128; s; s >>= 1) { if (t < s) red[t] = fmaxf(red[t], red[t+s]); __syncthreads(); }
    m = red[0]; __syncthreads();

    float ssum = 0.f;
    for (int i = start + t; i < end; i += 256) ssum += __expf(logits[i] - m);
    red[t] = ssum; __syncthreads();
    #pragma unroll
    for (int s = 128; s; s >>= 1) { if (t < s) red[t] += red[t+s]; __syncthreads(); }
    const float inv = 1.0f / red[0];
    __syncthreads();

    float acc = 0.f;
    for (int c0 = start; c0 < end; c0 += 256) {
        int i = c0 + t;
        __syncthreads();
        w[t] = (i < end) ? __expf(logits[i] - m) * inv : 0.f;
        __syncthreads();
        int cnt = min(256, end - c0);
        const float* xb = x + (size_t)c0 * DIM + t;
        int j = 0;
        for (; j + 3 < cnt; j += 4) {
            acc += w[j]     * xb[(size_t)j * DIM]
                 + w[j + 1] * xb[(size_t)(j + 1) * DIM]
                 + w[j + 2] * xb[(size_t)(j + 2) * DIM]
                 + w[j + 3] * xb[(size_t)(j + 3) * DIM];
        }
        for (; j < cnt; j++) acc += w[j] * xb[(size_t)j * DIM];
    }
    out[(size_t)g * DIM + t] = acc;
}

// ---------------- launch ----------------------------------------------------
extern "C" void kernel_launch(void* const* d_in, const int* in_sizes, int n_in,
                              void* d_out, int out_size)
{
    const float* X     = (const float*)d_in[0];
    const int*   batch = (const int*)d_in[1];
    const float* W1  = (const float*)d_in[3];
    const float* b1  = (const float*)d_in[4];
    const float* W2  = (const float*)d_in[5];
    const float* b2  = (const float*)d_in[6];
    const float* W3  = (const float*)d_in[7];
    const float* b3  = (const float*)d_in[8];
    const float* aW1 = (const float*)d_in[9];
    const float* ab1 = (const float*)d_in[10];
    const float* aW2 = (const float*)d_in[11];
    const float* ab2 = (const float*)d_in[12];
    float* out = (float*)d_out;

    const int N = in_sizes[0] / DIM;
    const int G = out_size / DIM;

    __nv_bfloat16 *Xhi, *Xlo, *Ahi, *Alo, *Bhi, *Blo, *Wt;
    float *fbuf, *logits, *att;
    cudaGetSymbolAddress((void**)&Xhi, g_Xhi);
    cudaGetSymbolAddress((void**)&Xlo, g_Xlo);
    cudaGetSymbolAddress((void**)&Ahi, g_Ahi);
    cudaGetSymbolAddress((void**)&Alo, g_Alo);
    cudaGetSymbolAddress((void**)&Bhi, g_Bhi);
    cudaGetSymbolAddress((void**)&Blo, g_Blo);
    cudaGetSymbolAddress((void**)&Wt,  g_Wt);
    cudaGetSymbolAddress((void**)&fbuf, g_f);
    cudaGetSymbolAddress((void**)&logits, g_logits);
    cudaGetSymbolAddress((void**)&att, g_att);

    __nv_bfloat16* W1h = Wt + 0 * DIM * DIM; __nv_bfloat16* W1l = Wt + 1 * DIM * DIM;
    __nv_bfloat16* W2h = Wt + 2 * DIM * DIM; __nv_bfloat16* W2l = Wt + 3 * DIM * DIM;
    __nv_bfloat16* W3h = Wt + 4 * DIM * DIM; __nv_bfloat16* W3l = Wt + 5 * DIM * DIM;
    __nv_bfloat16* WAh = Wt + 6 * DIM * DIM; __nv_bfloat16* WAl = Wt + 7 * DIM * DIM;

    cudaFuncSetAttribute(gemm_mma<MODE_SPLIT>, cudaFuncAttributeMaxDynamicSharedMemorySize, DYN_SMEM);
    cudaFuncSetAttribute(gemm_mma<MODE_F32>,   cudaFuncAttributeMaxDynamicSharedMemorySize, DYN_SMEM);
    cudaFuncSetAttribute(gemm_mma<MODE_ATT>,   cudaFuncAttributeMaxDynamicSharedMemorySize, DYN_SMEM);

    int n4 = N * (DIM / 4);
    xsplit_kernel<<<(n4 + 255) / 256, 256>>>((const float4*)X, (uint2*)Xhi, (uint2*)Xlo, n4);
    wsplit_all_kernel<<<dim3(DIM, 4), DIM>>>(W1, W2, W3, aW1, Wt);

    const int tiles = (N + BM - 1) / BM;
    dim3 grid(tiles, 2);

    // attention branch (partials per col-half, then combine)
    gemm_mma<MODE_ATT><<<grid, 256, DYN_SMEM>>>(Xhi, Xlo, WAh, WAl, ab1,
                                                nullptr, nullptr, nullptr,
                                                aW2, att, N);
    att_combine_kernel<<<(N + 255) / 256, 256>>>(att, att + NMAX, ab2, logits, N);

    // MLP trunk
    gemm_mma<MODE_SPLIT><<<grid, 256, DYN_SMEM>>>(Xhi, Xlo, W1h, W1l, b1,
                                                  nullptr, Ahi, Alo,
                                                  nullptr, nullptr, N);
    gemm_mma<MODE_SPLIT><<<grid, 256, DYN_SMEM>>>(Ahi, Alo, W2h, W2l, b2,
                                                  nullptr, Bhi, Blo,
                                                  nullptr, nullptr, N);
    gemm_mma<MODE_F32><<<grid, 256, DYN_SMEM>>>(Bhi, Blo, W3h, W3l, b3,
                                                fbuf, nullptr, nullptr,
                                                nullptr, nullptr, N);

    // softmax readout
    readout_kernel<<<G, 256>>>(fbuf, logits, batch, out, N);
}

// round 9
// speedup vs baseline: 2.2914x; 1.4854x over previous
#include <cuda_runtime.h>
#include <cuda_fp16.h>
#include <cstdint>
#include <cstddef>

// ===========================================================================
// InvariantReadout — fp16 2-MMA mma.sync (HMMA), round 9
//   A (activations) plain fp16; W split fp16 hi+lo (weights ~exact).
//   D = A*Bh + A*Bl : 2 MMAs per tile (was 3). Error = fp16 quant of A
//   (~1.4e-4/GEMM); total ~2-4e-4 << 1e-3 gate.
//   h1 = silu(X@W1+b1); h2 = silu(h1@W2+b2); x = h2@W3+b3
//   logits = silu(X@aW1+ab1)@aW2 + ab2 (fused epilogue, fp32 projection)
//   per-segment softmax -> weighted segment sum -> (G, 256)
// ===========================================================================

#define NMAX 200000
#define DIM  256
#define BM   128
#define BN   128
#define BKT  64                       // k-elems per stage
#define KTILES (DIM / BKT)            // 4
// Stage: A 128x64 fp16 (16KB) | Bh (16KB) | Bl (16KB)
#define OFF_BH   16384
#define OFF_BL   32768
#define STAGE    49152
#define DYN_SMEM (2 * STAGE)          // 96 KB -> 2 CTAs/SM

#define MODE_H    0   // silu -> fp16 out
#define MODE_F32  1   // bias only -> fp32 out
#define MODE_ATT  2   // silu, dot aW2 (fp32) -> per-col-half partial logits

// ---------------- scratch ---------------------------------------------------
__device__ __half g_Xh[(size_t)NMAX * DIM];
__device__ __half g_h1[(size_t)NMAX * DIM];
__device__ __half g_h2[(size_t)NMAX * DIM];
__device__ float  g_f[(size_t)NMAX * DIM];    // fp32 x
__device__ float  g_att[2][NMAX];             // per-col-half logit partials
__device__ float  g_logits[NMAX];
__device__ __half g_Wt[8][DIM * DIM];         // {W1,W2,W3,aW1} x {hi,lo}, n-major

// ---------------- helpers ---------------------------------------------------
__device__ __forceinline__ uint32_t smem_u32(const void* p) {
    uint32_t a;
    asm("{ .reg .u64 t; cvta.to.shared.u64 t, %1; cvt.u32.u64 %0, t; }" : "=r"(a) : "l"(p));
    return a;
}
__device__ __forceinline__ void cp16(uint32_t dst, const void* src) {
    asm volatile("cp.async.cg.shared.global [%0], [%1], 16;" :: "r"(dst), "l"(src) : "memory");
}
__device__ __forceinline__ void cp_commit() {
    asm volatile("cp.async.commit_group;" ::: "memory");
}
template <int NW>
__device__ __forceinline__ void cp_wait() {
    asm volatile("cp.async.wait_group %0;" :: "n"(NW) : "memory");
}
__device__ __forceinline__ void ldsm4(uint32_t* r, uint32_t addr) {
    asm volatile("ldmatrix.sync.aligned.m8n8.x4.shared.b16 {%0,%1,%2,%3}, [%4];"
                 : "=r"(r[0]), "=r"(r[1]), "=r"(r[2]), "=r"(r[3]) : "r"(addr));
}
__device__ __forceinline__ void mma16816(float* d, const uint32_t* a, const uint32_t* b) {
    asm volatile(
        "mma.sync.aligned.m16n8k16.row.col.f32.f16.f16.f32 "
        "{%0,%1,%2,%3}, {%4,%5,%6,%7}, {%8,%9}, {%0,%1,%2,%3};"
        : "+f"(d[0]), "+f"(d[1]), "+f"(d[2]), "+f"(d[3])
        : "r"(a[0]), "r"(a[1]), "r"(a[2]), "r"(a[3]), "r"(b[0]), "r"(b[1]));
}
__device__ __forceinline__ float silu_f(float x) { return x / (1.0f + __expf(-x)); }
__device__ __forceinline__ uint32_t h2_as_u32(__half2 h) {
    uint32_t u;
    *(__half2*)&u = h;
    return u;
}

// ---------------- prep kernels ---------------------------------------------
// X fp32 -> fp16
__global__ __launch_bounds__(256) void xhalf_kernel(
    const float4* __restrict__ X, uint2* __restrict__ Xh, int n4)
{
    int i = blockIdx.x * 256 + threadIdx.x;
    if (i >= n4) return;
    float4 v = X[i];
    Xh[i] = make_uint2(h2_as_u32(__floats2half2_rn(v.x, v.y)),
                       h2_as_u32(__floats2half2_rn(v.z, v.w)));
}

// all 4 weights: transpose + fp16 hi/lo split, n-major [n][k]
__global__ __launch_bounds__(256) void wsplit_all_kernel(
    const float* __restrict__ W1, const float* __restrict__ W2,
    const float* __restrict__ W3, const float* __restrict__ WA,
    __half* __restrict__ Wt)
{
    int n = blockIdx.x, k = threadIdx.x, w = blockIdx.y;
    const float* W = (w == 0) ? W1 : (w == 1) ? W2 : (w == 2) ? W3 : WA;
    float v = W[k * DIM + n];
    __half h = __float2half_rn(v);
    __half l = __float2half_rn(v - __half2float(h));
    Wt[(size_t)(2 * w)     * DIM * DIM + n * DIM + k] = h;
    Wt[(size_t)(2 * w + 1) * DIM * DIM + n * DIM + k] = l;
}

// combine attention partials -> logits
__global__ __launch_bounds__(256) void att_combine_kernel(
    const float* __restrict__ p0, const float* __restrict__ p1,
    const float* __restrict__ ab2, float* __restrict__ logits, int n)
{
    int i = blockIdx.x * 256 + threadIdx.x;
    if (i < n) logits[i] = p0[i] + p1[i] + ab2[0];
}

// ---------------- mma.sync GEMM (2 MMAs per k16) -----------------------------
template <int MODE>
__global__ __launch_bounds__(256, 2) void gemm_mma(
    const __half* __restrict__ A,
    const __half* __restrict__ Bh, const __half* __restrict__ Bl,
    const float* __restrict__ bias,
    float* __restrict__ Cf, __half* __restrict__ Ch,
    const float* __restrict__ aW2, float* __restrict__ attp, int nRows)
{
    extern __shared__ char sm[];
    __shared__ float s_bias[BN];
    __shared__ float s_aw2[BN];
    __shared__ float s_part[2][BM];

    const int tid  = threadIdx.x;
    const int wid  = tid >> 5;
    const int lane = tid & 31;
    const int warp_m = wid >> 1;        // 0..3 -> 32-row slab
    const int warp_n = wid & 1;         // 0..1 -> 64-col slab
    const int rowBase = blockIdx.x * BM;
    const int colBase = blockIdx.y * BN;

    if (tid < BN) {
        s_bias[tid] = bias[colBase + tid];
        if (MODE == MODE_ATT) s_aw2[tid] = aW2[colBase + tid];
    }

    const uint32_t smb = smem_u32(sm);

    auto load_stage = [&](int s, int kt) {
        const uint32_t st = smb + s * STAGE;
        const int ke = kt * BKT;
        #pragma unroll
        for (int i = 0; i < 4; i++) {                 // A: 1024 chunks
            int f = tid + i * 256;
            int r = f >> 3, c = f & 7;
            uint32_t off = (uint32_t)(r * 128 + ((c ^ (r & 7)) << 4));
            int gr = rowBase + r; if (gr >= nRows) gr = nRows - 1;
            cp16(st + off, A + (size_t)gr * DIM + ke + c * 8);
        }
        #pragma unroll
        for (int i = 0; i < 4; i++) {                 // Bh + Bl
            int f = tid + i * 256;
            int r = f >> 3, c = f & 7;
            uint32_t off = (uint32_t)(r * 128 + ((c ^ (r & 7)) << 4));
            size_t gb = (size_t)(colBase + r) * DIM + ke + c * 8;
            cp16(st + OFF_BH + off, Bh + gb);
            cp16(st + OFF_BL + off, Bl + gb);
        }
        cp_commit();
    };

    load_stage(0, 0);

    float acc[2][8][4];
    #pragma unroll
    for (int mt = 0; mt < 2; mt++)
        #pragma unroll
        for (int j = 0; j < 8; j++)
            #pragma unroll
            for (int q = 0; q < 4; q++) acc[mt][j][q] = 0.f;

    const int rrA = (lane & 7) + ((lane >> 3) & 1) * 8;
    const int khA = lane >> 4;
    const int rrB = (lane & 7) + (lane >> 4) * 8;
    const int khB = (lane >> 3) & 1;

    for (int kt = 0; kt < KTILES; kt++) {
        if (kt > 0) __syncthreads();                  // guard buf reuse
        if (kt + 1 < KTILES) load_stage((kt + 1) & 1, kt + 1);
        else cp_commit();
        cp_wait<1>();
        __syncthreads();

        const uint32_t ast = smb + (kt & 1) * STAGE;

        #pragma unroll
        for (int ks = 0; ks < 4; ks++) {              // 4 x k16 steps
            const int cA = ks * 2 + khA;
            const int cB = ks * 2 + khB;
            uint32_t ah[2][4];
            #pragma unroll
            for (int mt = 0; mt < 2; mt++) {
                int row = warp_m * 32 + mt * 16 + rrA;
                ldsm4(ah[mt], ast + row * 128 + ((cA ^ (row & 7)) << 4));
            }
            #pragma unroll
            for (int nt = 0; nt < 4; nt++) {
                int row = warp_n * 64 + nt * 16 + rrB;
                int r7 = row & 7;
                uint32_t bh[4], bl[4];
                ldsm4(bh, ast + OFF_BH + row * 128 + ((cB ^ r7) << 4));
                ldsm4(bl, ast + OFF_BL + row * 128 + ((cB ^ r7) << 4));
                #pragma unroll
                for (int mt = 0; mt < 2; mt++)
                    #pragma unroll
                    for (int h = 0; h < 2; h++) {
                        float* d = acc[mt][nt * 2 + h];
                        mma16816(d, ah[mt], &bh[h * 2]);   // A*Bh
                        mma16816(d, ah[mt], &bl[h * 2]);   // A*Bl
                    }
            }
        }
    }

    // ---- epilogue ----
    const int g  = lane >> 2;
    const int cp = (lane & 3) * 2;

    if (MODE == MODE_ATT) {
        float part[2][2] = {{0.f, 0.f}, {0.f, 0.f}};
        #pragma unroll
        for (int mt = 0; mt < 2; mt++)
            #pragma unroll
            for (int j = 0; j < 8; j++) {
                int lc = warp_n * 64 + j * 8 + cp;
                float bz0 = s_bias[lc], bz1 = s_bias[lc + 1];
                float w0 = s_aw2[lc],  w1 = s_aw2[lc + 1];
                #pragma unroll
                for (int hrow = 0; hrow < 2; hrow++) {
                    float v0 = silu_f(acc[mt][j][hrow * 2]     + bz0);
                    float v1 = silu_f(acc[mt][j][hrow * 2 + 1] + bz1);
                    part[mt][hrow] += v0 * w0 + v1 * w1;
                }
            }
        #pragma unroll
        for (int mt = 0; mt < 2; mt++)
            #pragma unroll
            for (int hrow = 0; hrow < 2; hrow++) {
                float p = part[mt][hrow];
                p += __shfl_xor_sync(0xFFFFFFFFu, p, 1);
                p += __shfl_xor_sync(0xFFFFFFFFu, p, 2);
                if ((lane & 3) == 0)
                    s_part[warp_n][warp_m * 32 + mt * 16 + hrow * 8 + g] = p;
            }
        __syncthreads();
        if (tid < BM) {
            int row = rowBase + tid;
            if (row < nRows)
                attp[(size_t)blockIdx.y * NMAX + row] =
                    s_part[0][tid] + s_part[1][tid];
        }
        return;
    }

    #pragma unroll
    for (int mt = 0; mt < 2; mt++) {
        int row0 = rowBase + warp_m * 32 + mt * 16 + g;
        #pragma unroll
        for (int j = 0; j < 8; j++) {
            int lc = warp_n * 64 + j * 8 + cp;
            float bz0 = s_bias[lc], bz1 = s_bias[lc + 1];
            #pragma unroll
            for (int hrow = 0; hrow < 2; hrow++) {
                int row = row0 + hrow * 8;
                if (row >= nRows) continue;
                float v0 = acc[mt][j][hrow * 2]     + bz0;
                float v1 = acc[mt][j][hrow * 2 + 1] + bz1;
                size_t o = (size_t)row * DIM + colBase + lc;
                if (MODE == MODE_H) {
                    v0 = silu_f(v0); v1 = silu_f(v1);
                    *(uint32_t*)(Ch + o) = h2_as_u32(__floats2half2_rn(v0, v1));
                } else {
                    *(float2*)(Cf + o) = make_float2(v0, v1);
                }
            }
        }
    }
}

// ---------------- segment softmax readout ----------------------------------
__device__ __forceinline__ int lower_bound_i(const int* __restrict__ a, int n, int v) {
    int lo = 0, hi = n;
    while (lo < hi) { int m = (lo + hi) >> 1; if (a[m] < v) lo = m + 1; else hi = m; }
    return lo;
}

__global__ __launch_bounds__(256) void readout_kernel(
    const float* __restrict__ x, const float* __restrict__ logits,
    const int* __restrict__ batch, float* __restrict__ out, int nRows)
{
    const int g = blockIdx.x, t = threadIdx.x;
    __shared__ float red[256];
    __shared__ float w[256];
    __shared__ int   srange[2];

    if (t == 0) srange[0] = lower_bound_i(batch, nRows, g);
    if (t == 1) srange[1] = lower_bound_i(batch, nRows, g + 1);
    __syncthreads();
    const int start = srange[0], end = srange[1];
    if (start >= end) { out[(size_t)g * DIM + t] = 0.f; return; }

    float m = -3.402823466e38f;
    for (int i = start + t; i < end; i += 256) m = fmaxf(m, logits[i]);
    red[t] = m; __syncthreads();
    #pragma unroll
    for (int s = 128; s; s >>= 1) { if (t < s) red[t] = fmaxf(red[t], red[t+s]); __syncthreads(); }
    m = red[0]; __syncthreads();

    float ssum = 0.f;
    for (int i = start + t; i < end; i += 256) ssum += __expf(logits[i] - m);
    red[t] = ssum; __syncthreads();
    #pragma unroll
    for (int s = 128; s; s >>= 1) { if (t < s) red[t] += red[t+s]; __syncthreads(); }
    const float inv = 1.0f / red[0];
    __syncthreads();

    float acc = 0.f;
    for (int c0 = start; c0 < end; c0 += 256) {
        int i = c0 + t;
        __syncthreads();
        w[t] = (i < end) ? __expf(logits[i] - m) * inv : 0.f;
        __syncthreads();
        int cnt = min(256, end - c0);
        const float* xb = x + (size_t)c0 * DIM + t;
        int j = 0;
        for (; j + 3 < cnt; j += 4) {
            acc += w[j]     * xb[(size_t)j * DIM]
                 + w[j + 1] * xb[(size_t)(j + 1) * DIM]
                 + w[j + 2] * xb[(size_t)(j + 2) * DIM]
                 + w[j + 3] * xb[(size_t)(j + 3) * DIM];
        }
        for (; j < cnt; j++) acc += w[j] * xb[(size_t)j * DIM];
    }
    out[(size_t)g * DIM + t] = acc;
}

// ---------------- launch ----------------------------------------------------
extern "C" void kernel_launch(void* const* d_in, const int* in_sizes, int n_in,
                              void* d_out, int out_size)
{
    const float* X     = (const float*)d_in[0];
    const int*   batch = (const int*)d_in[1];
    const float* W1  = (const float*)d_in[3];
    const float* b1  = (const float*)d_in[4];
    const float* W2  = (const float*)d_in[5];
    const float* b2  = (const float*)d_in[6];
    const float* W3  = (const float*)d_in[7];
    const float* b3  = (const float*)d_in[8];
    const float* aW1 = (const float*)d_in[9];
    const float* ab1 = (const float*)d_in[10];
    const float* aW2 = (const float*)d_in[11];
    const float* ab2 = (const float*)d_in[12];
    float* out = (float*)d_out;

    const int N = in_sizes[0] / DIM;
    const int G = out_size / DIM;

    __half *Xh, *h1, *h2, *Wt;
    float *fbuf, *logits, *att;
    cudaGetSymbolAddress((void**)&Xh, g_Xh);
    cudaGetSymbolAddress((void**)&h1, g_h1);
    cudaGetSymbolAddress((void**)&h2, g_h2);
    cudaGetSymbolAddress((void**)&Wt, g_Wt);
    cudaGetSymbolAddress((void**)&fbuf, g_f);
    cudaGetSymbolAddress((void**)&logits, g_logits);
    cudaGetSymbolAddress((void**)&att, g_att);

    __half* W1h = Wt + 0 * DIM * DIM; __half* W1l = Wt + 1 * DIM * DIM;
    __half* W2h = Wt + 2 * DIM * DIM; __half* W2l = Wt + 3 * DIM * DIM;
    __half* W3h = Wt + 4 * DIM * DIM; __half* W3l = Wt + 5 * DIM * DIM;
    __half* WAh = Wt + 6 * DIM * DIM; __half* WAl = Wt + 7 * DIM * DIM;

    cudaFuncSetAttribute(gemm_mma<MODE_H>,   cudaFuncAttributeMaxDynamicSharedMemorySize, DYN_SMEM);
    cudaFuncSetAttribute(gemm_mma<MODE_F32>, cudaFuncAttributeMaxDynamicSharedMemorySize, DYN_SMEM);
    cudaFuncSetAttribute(gemm_mma<MODE_ATT>, cudaFuncAttributeMaxDynamicSharedMemorySize, DYN_SMEM);

    int n4 = N * (DIM / 4);
    xhalf_kernel<<<(n4 + 255) / 256, 256>>>((const float4*)X, (uint2*)Xh, n4);
    wsplit_all_kernel<<<dim3(DIM, 4), DIM>>>(W1, W2, W3, aW1, Wt);

    const int tiles = (N + BM - 1) / BM;
    dim3 grid(tiles, 2);

    // attention branch (partials per col-half, then combine)
    gemm_mma<MODE_ATT><<<grid, 256, DYN_SMEM>>>(Xh, WAh, WAl, ab1,
                                                nullptr, nullptr, aW2, att, N);
    att_combine_kernel<<<(N + 255) / 256, 256>>>(att, att + NMAX, ab2, logits, N);

    // MLP trunk
    gemm_mma<MODE_H><<<grid, 256, DYN_SMEM>>>(Xh, W1h, W1l, b1,
                                              nullptr, h1, nullptr, nullptr, N);
    gemm_mma<MODE_H><<<grid, 256, DYN_SMEM>>>(h1, W2h, W2l, b2,
                                              nullptr, h2, nullptr, nullptr, N);
    gemm_mma<MODE_F32><<<grid, 256, DYN_SMEM>>>(h2, W3h, W3l, b3,
                                                fbuf, nullptr, nullptr, nullptr, N);

    // softmax readout
    readout_kernel<<<G, 256>>>(fbuf, logits, batch, out, N);
}

// round 10
// speedup vs baseline: 3.0879x; 1.3476x over previous
#include <cuda_runtime.h>
#include <cuda_fp16.h>
#include <cstdint>
#include <cstddef>

// ===========================================================================
// InvariantReadout — plain fp16 1-MMA mma.sync (HMMA), round 10
//   A and W both plain fp16, fp32 accumulate: 1 MMA per tile (was 2).
//   Error: fp16 quant of activations + weights ~1.5-3e-4 << 1e-3 gate.
//   h1 = silu(X@W1+b1); h2 = silu(h1@W2+b2); x = h2@W3+b3 (fp32 out)
//   logits = silu(X@aW1+ab1)@aW2 + ab2 (fused epilogue, fp32 projection)
//   per-segment softmax -> weighted segment sum -> (G, 256)
//   3-stage ring (R7 pattern), 96KB smem, 2 CTAs/SM.
// ===========================================================================

#define NMAX 200000
#define DIM  256
#define BM   128
#define BN   128
#define BKT  64                       // k-elems per stage
#define KTILES (DIM / BKT)            // 4
// Stage: A 128x64 fp16 (16KB) | B 128x64 fp16 (16KB)
#define OFF_B    16384
#define STAGE    32768
#define NSTAGE   3
#define DYN_SMEM (NSTAGE * STAGE)     // 96 KB -> 2 CTAs/SM

#define MODE_H    0   // silu -> fp16 out
#define MODE_F32  1   // bias only -> fp32 out
#define MODE_ATT  2   // silu, dot aW2 (fp32) -> per-col-half partial logits

// ---------------- scratch ---------------------------------------------------
__device__ __half g_Xh[(size_t)NMAX * DIM];
__device__ __half g_h1[(size_t)NMAX * DIM];
__device__ __half g_h2[(size_t)NMAX * DIM];
__device__ float  g_f[(size_t)NMAX * DIM];    // fp32 x
__device__ float  g_att[2][NMAX];             // per-col-half logit partials
__device__ float  g_logits[NMAX];
__device__ __half g_Wt[4][DIM * DIM];         // {W1,W2,W3,aW1} fp16, n-major

// ---------------- helpers ---------------------------------------------------
__device__ __forceinline__ uint32_t smem_u32(const void* p) {
    uint32_t a;
    asm("{ .reg .u64 t; cvta.to.shared.u64 t, %1; cvt.u32.u64 %0, t; }" : "=r"(a) : "l"(p));
    return a;
}
__device__ __forceinline__ void cp16(uint32_t dst, const void* src) {
    asm volatile("cp.async.cg.shared.global [%0], [%1], 16;" :: "r"(dst), "l"(src) : "memory");
}
__device__ __forceinline__ void cp_commit() {
    asm volatile("cp.async.commit_group;" ::: "memory");
}
template <int NW>
__device__ __forceinline__ void cp_wait() {
    asm volatile("cp.async.wait_group %0;" :: "n"(NW) : "memory");
}
__device__ __forceinline__ void ldsm4(uint32_t* r, uint32_t addr) {
    asm volatile("ldmatrix.sync.aligned.m8n8.x4.shared.b16 {%0,%1,%2,%3}, [%4];"
                 : "=r"(r[0]), "=r"(r[1]), "=r"(r[2]), "=r"(r[3]) : "r"(addr));
}
__device__ __forceinline__ void mma16816(float* d, const uint32_t* a, const uint32_t* b) {
    asm volatile(
        "mma.sync.aligned.m16n8k16.row.col.f32.f16.f16.f32 "
        "{%0,%1,%2,%3}, {%4,%5,%6,%7}, {%8,%9}, {%0,%1,%2,%3};"
        : "+f"(d[0]), "+f"(d[1]), "+f"(d[2]), "+f"(d[3])
        : "r"(a[0]), "r"(a[1]), "r"(a[2]), "r"(a[3]), "r"(b[0]), "r"(b[1]));
}
__device__ __forceinline__ float silu_f(float x) { return x / (1.0f + __expf(-x)); }
__device__ __forceinline__ uint32_t h2_as_u32(__half2 h) {
    uint32_t u;
    *(__half2*)&u = h;
    return u;
}

// ---------------- prep kernels ---------------------------------------------
// X fp32 -> fp16
__global__ __launch_bounds__(256) void xhalf_kernel(
    const float4* __restrict__ X, uint2* __restrict__ Xh, int n4)
{
    int i = blockIdx.x * 256 + threadIdx.x;
    if (i >= n4) return;
    float4 v = X[i];
    Xh[i] = make_uint2(h2_as_u32(__floats2half2_rn(v.x, v.y)),
                       h2_as_u32(__floats2half2_rn(v.z, v.w)));
}

// all 4 weights: transpose + fp16 convert, n-major [n][k]
__global__ __launch_bounds__(256) void wtrans_all_kernel(
    const float* __restrict__ W1, const float* __restrict__ W2,
    const float* __restrict__ W3, const float* __restrict__ WA,
    __half* __restrict__ Wt)
{
    int n = blockIdx.x, k = threadIdx.x, w = blockIdx.y;
    const float* W = (w == 0) ? W1 : (w == 1) ? W2 : (w == 2) ? W3 : WA;
    Wt[(size_t)w * DIM * DIM + n * DIM + k] = __float2half_rn(W[k * DIM + n]);
}

// combine attention partials -> logits
__global__ __launch_bounds__(256) void att_combine_kernel(
    const float* __restrict__ p0, const float* __restrict__ p1,
    const float* __restrict__ ab2, float* __restrict__ logits, int n)
{
    int i = blockIdx.x * 256 + threadIdx.x;
    if (i < n) logits[i] = p0[i] + p1[i] + ab2[0];
}

// ---------------- mma.sync GEMM (1 MMA per k16 tile) -------------------------
template <int MODE>
__global__ __launch_bounds__(256, 2) void gemm_mma(
    const __half* __restrict__ A, const __half* __restrict__ B,
    const float* __restrict__ bias,
    float* __restrict__ Cf, __half* __restrict__ Ch,
    const float* __restrict__ aW2, float* __restrict__ attp, int nRows)
{
    extern __shared__ char sm[];
    __shared__ float s_bias[BN];
    __shared__ float s_aw2[BN];
    __shared__ float s_part[2][BM];

    const int tid  = threadIdx.x;
    const int wid  = tid >> 5;
    const int lane = tid & 31;
    const int warp_m = wid >> 1;        // 0..3 -> 32-row slab
    const int warp_n = wid & 1;         // 0..1 -> 64-col slab
    const int rowBase = blockIdx.x * BM;
    const int colBase = blockIdx.y * BN;

    if (tid < BN) {
        s_bias[tid] = bias[colBase + tid];
        if (MODE == MODE_ATT) s_aw2[tid] = aW2[colBase + tid];
    }

    const uint32_t smb = smem_u32(sm);

    auto load_stage = [&](int s, int kt) {
        const uint32_t st = smb + s * STAGE;
        const int ke = kt * BKT;
        #pragma unroll
        for (int i = 0; i < 4; i++) {                 // 1024 chunks each tile
            int f = tid + i * 256;
            int r = f >> 3, c = f & 7;
            uint32_t off = (uint32_t)(r * 128 + ((c ^ (r & 7)) << 4));
            int gr = rowBase + r; if (gr >= nRows) gr = nRows - 1;
            cp16(st + off,         A + (size_t)gr * DIM + ke + c * 8);
            cp16(st + OFF_B + off, B + (size_t)(colBase + r) * DIM + ke + c * 8);
        }
        cp_commit();
    };

    load_stage(0, 0);
    load_stage(1, 1);

    float acc[2][8][4];
    #pragma unroll
    for (int mt = 0; mt < 2; mt++)
        #pragma unroll
        for (int j = 0; j < 8; j++)
            #pragma unroll
            for (int q = 0; q < 4; q++) acc[mt][j][q] = 0.f;

    const int rrA = (lane & 7) + ((lane >> 3) & 1) * 8;
    const int khA = lane >> 4;
    const int rrB = (lane & 7) + (lane >> 4) * 8;
    const int khB = (lane >> 3) & 1;

    int sbuf = 0;
    for (int kt = 0; kt < KTILES; kt++) {
        cp_wait<1>();                                 // stage kt complete
        __syncthreads();                              // all warps done with kt-1
        if (kt + 2 < KTILES) {
            int ns = sbuf + 2; if (ns >= NSTAGE) ns -= NSTAGE;
            load_stage(ns, kt + 2);
        } else {
            cp_commit();                              // keep group accounting
        }

        const uint32_t ast = smb + sbuf * STAGE;

        #pragma unroll
        for (int ks = 0; ks < 4; ks++) {              // 4 x k16 steps
            const int cA = ks * 2 + khA;
            const int cB = ks * 2 + khB;
            uint32_t ah[2][4];
            #pragma unroll
            for (int mt = 0; mt < 2; mt++) {
                int row = warp_m * 32 + mt * 16 + rrA;
                ldsm4(ah[mt], ast + row * 128 + ((cA ^ (row & 7)) << 4));
            }
            #pragma unroll
            for (int nt = 0; nt < 4; nt++) {
                int row = warp_n * 64 + nt * 16 + rrB;
                uint32_t bh[4];
                ldsm4(bh, ast + OFF_B + row * 128 + ((cB ^ (row & 7)) << 4));
                #pragma unroll
                for (int mt = 0; mt < 2; mt++)
                    #pragma unroll
                    for (int h = 0; h < 2; h++)
                        mma16816(acc[mt][nt * 2 + h], ah[mt], &bh[h * 2]);
            }
        }
        if (++sbuf >= NSTAGE) sbuf = 0;
    }

    // ---- epilogue ----
    const int g  = lane >> 2;
    const int cp = (lane & 3) * 2;

    if (MODE == MODE_ATT) {
        float part[2][2] = {{0.f, 0.f}, {0.f, 0.f}};
        #pragma unroll
        for (int mt = 0; mt < 2; mt++)
            #pragma unroll
            for (int j = 0; j < 8; j++) {
                int lc = warp_n * 64 + j * 8 + cp;
                float bz0 = s_bias[lc], bz1 = s_bias[lc + 1];
                float w0 = s_aw2[lc],  w1 = s_aw2[lc + 1];
                #pragma unroll
                for (int hrow = 0; hrow < 2; hrow++) {
                    float v0 = silu_f(acc[mt][j][hrow * 2]     + bz0);
                    float v1 = silu_f(acc[mt][j][hrow * 2 + 1] + bz1);
                    part[mt][hrow] += v0 * w0 + v1 * w1;
                }
            }
        #pragma unroll
        for (int mt = 0; mt < 2; mt++)
            #pragma unroll
            for (int hrow = 0; hrow < 2; hrow++) {
                float p = part[mt][hrow];
                p += __shfl_xor_sync(0xFFFFFFFFu, p, 1);
                p += __shfl_xor_sync(0xFFFFFFFFu, p, 2);
                if ((lane & 3) == 0)
                    s_part[warp_n][warp_m * 32 + mt * 16 + hrow * 8 + g] = p;
            }
        __syncthreads();
        if (tid < BM) {
            int row = rowBase + tid;
            if (row < nRows)
                attp[(size_t)blockIdx.y * NMAX + row] =
                    s_part[0][tid] + s_part[1][tid];
        }
        return;
    }

    #pragma unroll
    for (int mt = 0; mt < 2; mt++) {
        int row0 = rowBase + warp_m * 32 + mt * 16 + g;
        #pragma unroll
        for (int j = 0; j < 8; j++) {
            int lc = warp_n * 64 + j * 8 + cp;
            float bz0 = s_bias[lc], bz1 = s_bias[lc + 1];
            #pragma unroll
            for (int hrow = 0; hrow < 2; hrow++) {
                int row = row0 + hrow * 8;
                if (row >= nRows) continue;
                float v0 = acc[mt][j][hrow * 2]     + bz0;
                float v1 = acc[mt][j][hrow * 2 + 1] + bz1;
                size_t o = (size_t)row * DIM + colBase + lc;
                if (MODE == MODE_H) {
                    v0 = silu_f(v0); v1 = silu_f(v1);
                    *(uint32_t*)(Ch + o) = h2_as_u32(__floats2half2_rn(v0, v1));
                } else {
                    *(float2*)(Cf + o) = make_float2(v0, v1);
                }
            }
        }
    }
}

// ---------------- segment softmax readout ----------------------------------
__device__ __forceinline__ int lower_bound_i(const int* __restrict__ a, int n, int v) {
    int lo = 0, hi = n;
    while (lo < hi) { int m = (lo + hi) >> 1; if (a[m] < v) lo = m + 1; else hi = m; }
    return lo;
}

__global__ __launch_bounds__(256) void readout_kernel(
    const float* __restrict__ x, const float* __restrict__ logits,
    const int* __restrict__ batch, float* __restrict__ out, int nRows)
{
    const int g = blockIdx.x, t = threadIdx.x;
    __shared__ float red[256];
    __shared__ float w[256];
    __shared__ int   srange[2];

    if (t == 0) srange[0] = lower_bound_i(batch, nRows, g);
    if (t == 1) srange[1] = lower_bound_i(batch, nRows, g + 1);
    __syncthreads();
    const int start = srange[0], end = srange[1];
    if (start >= end) { out[(size_t)g * DIM + t] = 0.f; return; }

    float m = -3.402823466e38f;
    for (int i = start + t; i < end; i += 256) m = fmaxf(m, logits[i]);
    red[t] = m; __syncthreads();
    #pragma unroll
    for (int s = 128; s; s >>= 1) { if (t < s) red[t] = fmaxf(red[t], red[t+s]); __syncthreads(); }
    m = red[0]; __syncthreads();

    float ssum = 0.f;
    for (int i = start + t; i < end; i += 256) ssum += __expf(logits[i] - m);
    red[t] = ssum; __syncthreads();
    #pragma unroll
    for (int s = 128; s; s >>= 1) { if (t < s) red[t] += red[t+s]; __syncthreads(); }
    const float inv = 1.0f / red[0];
    __syncthreads();

    float acc = 0.f;
    for (int c0 = start; c0 < end; c0 += 256) {
        int i = c0 + t;
        __syncthreads();
        w[t] = (i < end) ? __expf(logits[i] - m) * inv : 0.f;
        __syncthreads();
        int cnt = min(256, end - c0);
        const float* xb = x + (size_t)c0 * DIM + t;
        int j = 0;
        for (; j + 3 < cnt; j += 4) {
            acc += w[j]     * xb[(size_t)j * DIM]
                 + w[j + 1] * xb[(size_t)(j + 1) * DIM]
                 + w[j + 2] * xb[(size_t)(j + 2) * DIM]
                 + w[j + 3] * xb[(size_t)(j + 3) * DIM];
        }
        for (; j < cnt; j++) acc += w[j] * xb[(size_t)j * DIM];
    }
    out[(size_t)g * DIM + t] = acc;
}

// ---------------- launch ----------------------------------------------------
extern "C" void kernel_launch(void* const* d_in, const int* in_sizes, int n_in,
                              void* d_out, int out_size)
{
    const float* X     = (const float*)d_in[0];
    const int*   batch = (const int*)d_in[1];
    const float* W1  = (const float*)d_in[3];
    const float* b1  = (const float*)d_in[4];
    const float* W2  = (const float*)d_in[5];
    const float* b2  = (const float*)d_in[6];
    const float* W3  = (const float*)d_in[7];
    const float* b3  = (const float*)d_in[8];
    const float* aW1 = (const float*)d_in[9];
    const float* ab1 = (const float*)d_in[10];
    const float* aW2 = (const float*)d_in[11];
    const float* ab2 = (const float*)d_in[12];
    float* out = (float*)d_out;

    const int N = in_sizes[0] / DIM;
    const int G = out_size / DIM;

    __half *Xh, *h1, *h2, *Wt;
    float *fbuf, *logits, *att;
    cudaGetSymbolAddress((void**)&Xh, g_Xh);
    cudaGetSymbolAddress((void**)&h1, g_h1);
    cudaGetSymbolAddress((void**)&h2, g_h2);
    cudaGetSymbolAddress((void**)&Wt, g_Wt);
    cudaGetSymbolAddress((void**)&fbuf, g_f);
    cudaGetSymbolAddress((void**)&logits, g_logits);
    cudaGetSymbolAddress((void**)&att, g_att);

    __half* W1t = Wt + 0 * DIM * DIM;
    __half* W2t = Wt + 1 * DIM * DIM;
    __half* W3t = Wt + 2 * DIM * DIM;
    __half* WAt = Wt + 3 * DIM * DIM;

    cudaFuncSetAttribute(gemm_mma<MODE_H>,   cudaFuncAttributeMaxDynamicSharedMemorySize, DYN_SMEM);
    cudaFuncSetAttribute(gemm_mma<MODE_F32>, cudaFuncAttributeMaxDynamicSharedMemorySize, DYN_SMEM);
    cudaFuncSetAttribute(gemm_mma<MODE_ATT>, cudaFuncAttributeMaxDynamicSharedMemorySize, DYN_SMEM);

    int n4 = N * (DIM / 4);
    xhalf_kernel<<<(n4 + 255) / 256, 256>>>((const float4*)X, (uint2*)Xh, n4);
    wtrans_all_kernel<<<dim3(DIM, 4), DIM>>>(W1, W2, W3, aW1, Wt);

    const int tiles = (N + BM - 1) / BM;
    dim3 grid(tiles, 2);

    // attention branch (partials per col-half, then combine)
    gemm_mma<MODE_ATT><<<grid, 256, DYN_SMEM>>>(Xh, WAt, ab1,
                                                nullptr, nullptr, aW2, att, N);
    att_combine_kernel<<<(N + 255) / 256, 256>>>(att, att + NMAX, ab2, logits, N);

    // MLP trunk
    gemm_mma<MODE_H><<<grid, 256, DYN_SMEM>>>(Xh, W1t, b1,
                                              nullptr, h1, nullptr, nullptr, N);
    gemm_mma<MODE_H><<<grid, 256, DYN_SMEM>>>(h1, W2t, b2,
                                              nullptr, h2, nullptr, nullptr, N);
    gemm_mma<MODE_F32><<<grid, 256, DYN_SMEM>>>(h2, W3t, b3,
                                                fbuf, nullptr, nullptr, nullptr, N);

    // softmax readout
    readout_kernel<<<G, 256>>>(fbuf, logits, batch, out, N);
}

// round 11
// speedup vs baseline: 3.1815x; 1.0303x over previous
#include <cuda_runtime.h>
#include <cuda_fp16.h>
#include <cstdint>
#include <cstddef>

// ===========================================================================
// InvariantReadout — plain fp16 1-MMA mma.sync (HMMA), round 11
//   Memory-traffic round: grid-transposed for A L2 reuse, att+W1 GEMMs fused
//   into one launch (4 parts), x stored fp16.
//   h1 = silu(X@W1+b1); h2 = silu(h1@W2+b2); x = h2@W3+b3 (fp16 out)
//   logits = silu(X@aW1+ab1)@aW2 + ab2 (fused epilogue, fp32 projection)
//   per-segment softmax -> weighted segment sum -> (G, 256)
// ===========================================================================

#define NMAX 200000
#define DIM  256
#define BM   128
#define BN   128
#define BKT  64                       // k-elems per stage
#define KTILES (DIM / BKT)            // 4
#define OFF_B    16384
#define STAGE    32768
#define NSTAGE   3
#define DYN_SMEM (NSTAGE * STAGE)     // 96 KB -> 2 CTAs/SM

// ---------------- scratch ---------------------------------------------------
__device__ __half g_Xh[(size_t)NMAX * DIM];
__device__ __half g_h1[(size_t)NMAX * DIM];   // h1, later reused for x (fp16)
__device__ __half g_h2[(size_t)NMAX * DIM];
__device__ float  g_att[2][NMAX];             // per-col-half logit partials
__device__ float  g_logits[NMAX];
__device__ __half g_Wt[4][DIM * DIM];         // {W1,W2,W3,aW1} fp16, n-major

// ---------------- helpers ---------------------------------------------------
__device__ __forceinline__ uint32_t smem_u32(const void* p) {
    uint32_t a;
    asm("{ .reg .u64 t; cvta.to.shared.u64 t, %1; cvt.u32.u64 %0, t; }" : "=r"(a) : "l"(p));
    return a;
}
__device__ __forceinline__ void cp16(uint32_t dst, const void* src) {
    asm volatile("cp.async.cg.shared.global [%0], [%1], 16;" :: "r"(dst), "l"(src) : "memory");
}
__device__ __forceinline__ void cp_commit() {
    asm volatile("cp.async.commit_group;" ::: "memory");
}
template <int NW>
__device__ __forceinline__ void cp_wait() {
    asm volatile("cp.async.wait_group %0;" :: "n"(NW) : "memory");
}
__device__ __forceinline__ void ldsm4(uint32_t* r, uint32_t addr) {
    asm volatile("ldmatrix.sync.aligned.m8n8.x4.shared.b16 {%0,%1,%2,%3}, [%4];"
                 : "=r"(r[0]), "=r"(r[1]), "=r"(r[2]), "=r"(r[3]) : "r"(addr));
}
__device__ __forceinline__ void mma16816(float* d, const uint32_t* a, const uint32_t* b) {
    asm volatile(
        "mma.sync.aligned.m16n8k16.row.col.f32.f16.f16.f32 "
        "{%0,%1,%2,%3}, {%4,%5,%6,%7}, {%8,%9}, {%0,%1,%2,%3};"
        : "+f"(d[0]), "+f"(d[1]), "+f"(d[2]), "+f"(d[3])
        : "r"(a[0]), "r"(a[1]), "r"(a[2]), "r"(a[3]), "r"(b[0]), "r"(b[1]));
}
__device__ __forceinline__ float silu_f(float x) { return x / (1.0f + __expf(-x)); }
__device__ __forceinline__ uint32_t h2_as_u32(__half2 h) {
    uint32_t u;
    *(__half2*)&u = h;
    return u;
}

// ---------------- prep kernels ---------------------------------------------
__global__ __launch_bounds__(256) void xhalf_kernel(
    const float4* __restrict__ X, uint2* __restrict__ Xh, int n4)
{
    int i = blockIdx.x * 256 + threadIdx.x;
    if (i >= n4) return;
    float4 v = X[i];
    Xh[i] = make_uint2(h2_as_u32(__floats2half2_rn(v.x, v.y)),
                       h2_as_u32(__floats2half2_rn(v.z, v.w)));
}

__global__ __launch_bounds__(256) void wtrans_all_kernel(
    const float* __restrict__ W1, const float* __restrict__ W2,
    const float* __restrict__ W3, const float* __restrict__ WA,
    __half* __restrict__ Wt)
{
    int n = blockIdx.x, k = threadIdx.x, w = blockIdx.y;
    const float* W = (w == 0) ? W1 : (w == 1) ? W2 : (w == 2) ? W3 : WA;
    Wt[(size_t)w * DIM * DIM + n * DIM + k] = __float2half_rn(W[k * DIM + n]);
}

__global__ __launch_bounds__(256) void att_combine_kernel(
    const float* __restrict__ p0, const float* __restrict__ p1,
    const float* __restrict__ ab2, float* __restrict__ logits, int n)
{
    int i = blockIdx.x * 256 + threadIdx.x;
    if (i < n) logits[i] = p0[i] + p1[i] + ab2[0];
}

// ---------------- mma.sync GEMM (1 MMA per k16 tile) -------------------------
// grid(nparts, tiles): blockIdx.x = part (fastest -> A L2 reuse),
// blockIdx.y = row tile. parts 0,1: normal epilogue (col halves of B0/bias0,
// silu per do_silu, fp16 out). parts 2,3: ATT epilogue (B1/bias1, aW2 dot).
__global__ __launch_bounds__(256, 2) void gemm_mma(
    const __half* __restrict__ A,
    const __half* __restrict__ B0, const __half* __restrict__ B1,
    const float* __restrict__ bias0, const float* __restrict__ bias1,
    __half* __restrict__ Ch,
    const float* __restrict__ aW2, float* __restrict__ attp,
    int nRows, int do_silu)
{
    extern __shared__ char sm[];
    __shared__ float s_bias[BN];
    __shared__ float s_aw2[BN];
    __shared__ float s_part[2][BM];

    const int tid  = threadIdx.x;
    const int wid  = tid >> 5;
    const int lane = tid & 31;
    const int warp_m = wid >> 1;
    const int warp_n = wid & 1;
    const int part = blockIdx.x;
    const bool is_att = (part >= 2);
    const int colBase = (part & 1) * BN;
    const int rowBase = blockIdx.y * BM;

    const __half* B    = is_att ? B1 : B0;
    const float*  bias = is_att ? bias1 : bias0;

    if (tid < BN) {
        s_bias[tid] = bias[colBase + tid];
        if (is_att) s_aw2[tid] = aW2[colBase + tid];
    }

    const uint32_t smb = smem_u32(sm);

    auto load_stage = [&](int s, int kt) {
        const uint32_t st = smb + s * STAGE;
        const int ke = kt * BKT;
        #pragma unroll
        for (int i = 0; i < 4; i++) {
            int f = tid + i * 256;
            int r = f >> 3, c = f & 7;
            uint32_t off = (uint32_t)(r * 128 + ((c ^ (r & 7)) << 4));
            int gr = rowBase + r; if (gr >= nRows) gr = nRows - 1;
            cp16(st + off,         A + (size_t)gr * DIM + ke + c * 8);
            cp16(st + OFF_B + off, B + (size_t)(colBase + r) * DIM + ke + c * 8);
        }
        cp_commit();
    };

    load_stage(0, 0);
    load_stage(1, 1);

    float acc[2][8][4];
    #pragma unroll
    for (int mt = 0; mt < 2; mt++)
        #pragma unroll
        for (int j = 0; j < 8; j++)
            #pragma unroll
            for (int q = 0; q < 4; q++) acc[mt][j][q] = 0.f;

    const int rrA = (lane & 7) + ((lane >> 3) & 1) * 8;
    const int khA = lane >> 4;
    const int rrB = (lane & 7) + (lane >> 4) * 8;
    const int khB = (lane >> 3) & 1;

    int sbuf = 0;
    for (int kt = 0; kt < KTILES; kt++) {
        cp_wait<1>();
        __syncthreads();
        if (kt + 2 < KTILES) {
            int ns = sbuf + 2; if (ns >= NSTAGE) ns -= NSTAGE;
            load_stage(ns, kt + 2);
        } else {
            cp_commit();
        }

        const uint32_t ast = smb + sbuf * STAGE;

        #pragma unroll
        for (int ks = 0; ks < 4; ks++) {
            const int cA = ks * 2 + khA;
            const int cB = ks * 2 + khB;
            uint32_t ah[2][4];
            #pragma unroll
            for (int mt = 0; mt < 2; mt++) {
                int row = warp_m * 32 + mt * 16 + rrA;
                ldsm4(ah[mt], ast + row * 128 + ((cA ^ (row & 7)) << 4));
            }
            #pragma unroll
            for (int nt = 0; nt < 4; nt++) {
                int row = warp_n * 64 + nt * 16 + rrB;
                uint32_t bh[4];
                ldsm4(bh, ast + OFF_B + row * 128 + ((cB ^ (row & 7)) << 4));
                #pragma unroll
                for (int mt = 0; mt < 2; mt++)
                    #pragma unroll
                    for (int h = 0; h < 2; h++)
                        mma16816(acc[mt][nt * 2 + h], ah[mt], &bh[h * 2]);
            }
        }
        if (++sbuf >= NSTAGE) sbuf = 0;
    }

    // ---- epilogue ----
    const int g  = lane >> 2;
    const int cp = (lane & 3) * 2;

    if (is_att) {
        float part2[2][2] = {{0.f, 0.f}, {0.f, 0.f}};
        #pragma unroll
        for (int mt = 0; mt < 2; mt++)
            #pragma unroll
            for (int j = 0; j < 8; j++) {
                int lc = warp_n * 64 + j * 8 + cp;
                float bz0 = s_bias[lc], bz1 = s_bias[lc + 1];
                float w0 = s_aw2[lc],  w1 = s_aw2[lc + 1];
                #pragma unroll
                for (int hrow = 0; hrow < 2; hrow++) {
                    float v0 = silu_f(acc[mt][j][hrow * 2]     + bz0);
                    float v1 = silu_f(acc[mt][j][hrow * 2 + 1] + bz1);
                    part2[mt][hrow] += v0 * w0 + v1 * w1;
                }
            }
        #pragma unroll
        for (int mt = 0; mt < 2; mt++)
            #pragma unroll
            for (int hrow = 0; hrow < 2; hrow++) {
                float p = part2[mt][hrow];
                p += __shfl_xor_sync(0xFFFFFFFFu, p, 1);
                p += __shfl_xor_sync(0xFFFFFFFFu, p, 2);
                if ((lane & 3) == 0)
                    s_part[warp_n][warp_m * 32 + mt * 16 + hrow * 8 + g] = p;
            }
        __syncthreads();
        if (tid < BM) {
            int row = rowBase + tid;
            if (row < nRows)
                attp[(size_t)(part - 2) * NMAX + row] =
                    s_part[0][tid] + s_part[1][tid];
        }
        return;
    }

    #pragma unroll
    for (int mt = 0; mt < 2; mt++) {
        int row0 = rowBase + warp_m * 32 + mt * 16 + g;
        #pragma unroll
        for (int j = 0; j < 8; j++) {
            int lc = warp_n * 64 + j * 8 + cp;
            float bz0 = s_bias[lc], bz1 = s_bias[lc + 1];
            #pragma unroll
            for (int hrow = 0; hrow < 2; hrow++) {
                int row = row0 + hrow * 8;
                if (row >= nRows) continue;
                float v0 = acc[mt][j][hrow * 2]     + bz0;
                float v1 = acc[mt][j][hrow * 2 + 1] + bz1;
                if (do_silu) { v0 = silu_f(v0); v1 = silu_f(v1); }
                size_t o = (size_t)row * DIM + colBase + lc;
                *(uint32_t*)(Ch + o) = h2_as_u32(__floats2half2_rn(v0, v1));
            }
        }
    }
}

// ---------------- segment softmax readout (x in fp16) -----------------------
__device__ __forceinline__ int lower_bound_i(const int* __restrict__ a, int n, int v) {
    int lo = 0, hi = n;
    while (lo < hi) { int m = (lo + hi) >> 1; if (a[m] < v) lo = m + 1; else hi = m; }
    return lo;
}

__global__ __launch_bounds__(256) void readout_kernel(
    const __half* __restrict__ x, const float* __restrict__ logits,
    const int* __restrict__ batch, float* __restrict__ out, int nRows)
{
    const int g = blockIdx.x, t = threadIdx.x;
    __shared__ float red[256];
    __shared__ float w[256];
    __shared__ int   srange[2];

    if (t == 0) srange[0] = lower_bound_i(batch, nRows, g);
    if (t == 1) srange[1] = lower_bound_i(batch, nRows, g + 1);
    __syncthreads();
    const int start = srange[0], end = srange[1];
    if (start >= end) { out[(size_t)g * DIM + t] = 0.f; return; }

    float m = -3.402823466e38f;
    for (int i = start + t; i < end; i += 256) m = fmaxf(m, logits[i]);
    red[t] = m; __syncthreads();
    #pragma unroll
    for (int s = 128; s; s >>= 1) { if (t < s) red[t] = fmaxf(red[t], red[t+s]); __syncthreads(); }
    m = red[0]; __syncthreads();

    float ssum = 0.f;
    for (int i = start + t; i < end; i += 256) ssum += __expf(logits[i] - m);
    red[t] = ssum; __syncthreads();
    #pragma unroll
    for (int s = 128; s; s >>= 1) { if (t < s) red[t] += red[t+s]; __syncthreads(); }
    const float inv = 1.0f / red[0];
    __syncthreads();

    float acc = 0.f;
    for (int c0 = start; c0 < end; c0 += 256) {
        int i = c0 + t;
        __syncthreads();
        w[t] = (i < end) ? __expf(logits[i] - m) * inv : 0.f;
        __syncthreads();
        int cnt = min(256, end - c0);
        const __half* xb = x + (size_t)c0 * DIM + t;
        int j = 0;
        for (; j + 3 < cnt; j += 4) {
            acc += w[j]     * __half2float(xb[(size_t)j * DIM])
                 + w[j + 1] * __half2float(xb[(size_t)(j + 1) * DIM])
                 + w[j + 2] * __half2float(xb[(size_t)(j + 2) * DIM])
                 + w[j + 3] * __half2float(xb[(size_t)(j + 3) * DIM]);
        }
        for (; j < cnt; j++) acc += w[j] * __half2float(xb[(size_t)j * DIM]);
    }
    out[(size_t)g * DIM + t] = acc;
}

// ---------------- launch ----------------------------------------------------
extern "C" void kernel_launch(void* const* d_in, const int* in_sizes, int n_in,
                              void* d_out, int out_size)
{
    const float* X     = (const float*)d_in[0];
    const int*   batch = (const int*)d_in[1];
    const float* W1  = (const float*)d_in[3];
    const float* b1  = (const float*)d_in[4];
    const float* W2  = (const float*)d_in[5];
    const float* b2  = (const float*)d_in[6];
    const float* W3  = (const float*)d_in[7];
    const float* b3  = (const float*)d_in[8];
    const float* aW1 = (const float*)d_in[9];
    const float* ab1 = (const float*)d_in[10];
    const float* aW2 = (const float*)d_in[11];
    const float* ab2 = (const float*)d_in[12];
    float* out = (float*)d_out;

    const int N = in_sizes[0] / DIM;
    const int G = out_size / DIM;

    __half *Xh, *h1, *h2, *Wt;
    float *logits, *att;
    cudaGetSymbolAddress((void**)&Xh, g_Xh);
    cudaGetSymbolAddress((void**)&h1, g_h1);
    cudaGetSymbolAddress((void**)&h2, g_h2);
    cudaGetSymbolAddress((void**)&Wt, g_Wt);
    cudaGetSymbolAddress((void**)&logits, g_logits);
    cudaGetSymbolAddress((void**)&att, g_att);

    __half* W1t = Wt + 0 * DIM * DIM;
    __half* W2t = Wt + 1 * DIM * DIM;
    __half* W3t = Wt + 2 * DIM * DIM;
    __half* WAt = Wt + 3 * DIM * DIM;

    cudaFuncSetAttribute(gemm_mma, cudaFuncAttributeMaxDynamicSharedMemorySize, DYN_SMEM);

    int n4 = N * (DIM / 4);
    xhalf_kernel<<<(n4 + 255) / 256, 256>>>((const float4*)X, (uint2*)Xh, n4);
    wtrans_all_kernel<<<dim3(DIM, 4), DIM>>>(W1, W2, W3, aW1, Wt);

    const int tiles = (N + BM - 1) / BM;

    // fused: W1 GEMM (parts 0,1 -> h1) + attention GEMM (parts 2,3 -> att)
    gemm_mma<<<dim3(4, tiles), 256, DYN_SMEM>>>(Xh, W1t, WAt, b1, ab1,
                                                h1, aW2, att, N, 1);
    att_combine_kernel<<<(N + 255) / 256, 256>>>(att, att + NMAX, ab2, logits, N);

    // h2 = silu(h1@W2+b2)
    gemm_mma<<<dim3(2, tiles), 256, DYN_SMEM>>>(h1, W2t, W2t, b2, b2,
                                                h2, aW2, att, N, 1);
    // x = h2@W3+b3 (fp16, into g_h1 which is dead now)
    gemm_mma<<<dim3(2, tiles), 256, DYN_SMEM>>>(h2, W3t, W3t, b3, b3,
                                                h1, aW2, att, N, 0);

    // softmax readout over fp16 x
    readout_kernel<<<G, 256>>>(h1, logits, batch, out, N);
}

// round 12
// speedup vs baseline: 3.2866x; 1.0330x over previous
#include <cuda_runtime.h>
#include <cuda_fp16.h>
#include <cstdint>
#include <cstddef>

// ===========================================================================
// InvariantReadout — plain fp16 1-MMA mma.sync (HMMA), round 12
//   Readout fused into GEMM3: per-tile weighted segment partials (determin-
//   istic, no atomics), tiny combine kernel. x never hits DRAM.
//   h1 = silu(X@W1+b1); h2 = silu(h1@W2+b2); x = h2@W3+b3 (never stored)
//   logits = silu(X@aW1+ab1)@aW2 + ab2 (fused epilogue partials)
//   weights kernel: per-segment softmax -> w[i]
//   GEMM3 epilogue: sum_i w[i]*x[i] per (tile, segment-slot, col)
// ===========================================================================

#define NMAX 200000
#define DIM  256
#define BM   128
#define BN   128
#define BKT  64
#define KTILES (DIM / BKT)            // 4
#define OFF_B    16384
#define STAGE    32768
#define NSTAGE   3
#define DYN_SMEM (NSTAGE * STAGE)     // 96 KB -> 2 CTAs/SM
#define TILESMAX ((NMAX + BM - 1) / BM)
#define XW_STRIDE 130                 // padded fp32 row stride in smem tile

// ---------------- scratch ---------------------------------------------------
__device__ __half g_Xh[(size_t)NMAX * DIM];
__device__ __half g_h1[(size_t)NMAX * DIM];
__device__ __half g_h2[(size_t)NMAX * DIM];
__device__ float  g_att[2][NMAX];             // per-col-half logit partials
__device__ float  g_w[NMAX];                  // softmax weights
__device__ float  g_rpart[(size_t)TILESMAX * 2 * DIM];  // per-tile partials
__device__ __half g_Wt[4][DIM * DIM];         // {W1,W2,W3,aW1} fp16, n-major

// ---------------- helpers ---------------------------------------------------
__device__ __forceinline__ uint32_t smem_u32(const void* p) {
    uint32_t a;
    asm("{ .reg .u64 t; cvta.to.shared.u64 t, %1; cvt.u32.u64 %0, t; }" : "=r"(a) : "l"(p));
    return a;
}
__device__ __forceinline__ void cp16(uint32_t dst, const void* src) {
    asm volatile("cp.async.cg.shared.global [%0], [%1], 16;" :: "r"(dst), "l"(src) : "memory");
}
__device__ __forceinline__ void cp_commit() {
    asm volatile("cp.async.commit_group;" ::: "memory");
}
template <int NW>
__device__ __forceinline__ void cp_wait() {
    asm volatile("cp.async.wait_group %0;" :: "n"(NW) : "memory");
}
__device__ __forceinline__ void ldsm4(uint32_t* r, uint32_t addr) {
    asm volatile("ldmatrix.sync.aligned.m8n8.x4.shared.b16 {%0,%1,%2,%3}, [%4];"
                 : "=r"(r[0]), "=r"(r[1]), "=r"(r[2]), "=r"(r[3]) : "r"(addr));
}
__device__ __forceinline__ void mma16816(float* d, const uint32_t* a, const uint32_t* b) {
    asm volatile(
        "mma.sync.aligned.m16n8k16.row.col.f32.f16.f16.f32 "
        "{%0,%1,%2,%3}, {%4,%5,%6,%7}, {%8,%9}, {%0,%1,%2,%3};"
        : "+f"(d[0]), "+f"(d[1]), "+f"(d[2]), "+f"(d[3])
        : "r"(a[0]), "r"(a[1]), "r"(a[2]), "r"(a[3]), "r"(b[0]), "r"(b[1]));
}
__device__ __forceinline__ float silu_f(float x) { return x / (1.0f + __expf(-x)); }
__device__ __forceinline__ uint32_t h2_as_u32(__half2 h) {
    uint32_t u;
    *(__half2*)&u = h;
    return u;
}
__device__ __forceinline__ int lower_bound_i(const int* __restrict__ a, int n, int v) {
    int lo = 0, hi = n;
    while (lo < hi) { int m = (lo + hi) >> 1; if (a[m] < v) lo = m + 1; else hi = m; }
    return lo;
}

// ---------------- prep kernels ---------------------------------------------
__global__ __launch_bounds__(256) void xhalf_kernel(
    const float4* __restrict__ X, uint2* __restrict__ Xh, int n4)
{
    int i = blockIdx.x * 256 + threadIdx.x;
    if (i >= n4) return;
    float4 v = X[i];
    Xh[i] = make_uint2(h2_as_u32(__floats2half2_rn(v.x, v.y)),
                       h2_as_u32(__floats2half2_rn(v.z, v.w)));
}

__global__ __launch_bounds__(256) void wtrans_all_kernel(
    const float* __restrict__ W1, const float* __restrict__ W2,
    const float* __restrict__ W3, const float* __restrict__ WA,
    __half* __restrict__ Wt)
{
    int n = blockIdx.x, k = threadIdx.x, w = blockIdx.y;
    const float* W = (w == 0) ? W1 : (w == 1) ? W2 : (w == 2) ? W3 : WA;
    Wt[(size_t)w * DIM * DIM + n * DIM + k] = __float2half_rn(W[k * DIM + n]);
}

// weights: per-segment softmax over logits = p0 + p1 + ab2
__global__ __launch_bounds__(256) void weights_kernel(
    const float* __restrict__ p0, const float* __restrict__ p1,
    const float* __restrict__ ab2, const int* __restrict__ batch,
    float* __restrict__ wout, int nRows)
{
    const int g = blockIdx.x, t = threadIdx.x;
    __shared__ float red[256];
    __shared__ int   srange[2];
    if (t == 0) srange[0] = lower_bound_i(batch, nRows, g);
    if (t == 1) srange[1] = lower_bound_i(batch, nRows, g + 1);
    __syncthreads();
    const int start = srange[0], end = srange[1];
    if (start >= end) return;
    const float bb = ab2[0];

    float m = -3.402823466e38f;
    for (int i = start + t; i < end; i += 256)
        m = fmaxf(m, p0[i] + p1[i] + bb);
    red[t] = m; __syncthreads();
    #pragma unroll
    for (int s = 128; s; s >>= 1) { if (t < s) red[t] = fmaxf(red[t], red[t+s]); __syncthreads(); }
    m = red[0]; __syncthreads();

    float ssum = 0.f;
    for (int i = start + t; i < end; i += 256)
        ssum += __expf(p0[i] + p1[i] + bb - m);
    red[t] = ssum; __syncthreads();
    #pragma unroll
    for (int s = 128; s; s >>= 1) { if (t < s) red[t] += red[t+s]; __syncthreads(); }
    const float inv = 1.0f / red[0];

    for (int i = start + t; i < end; i += 256)
        wout[i] = __expf(p0[i] + p1[i] + bb - m) * inv;
}

// combine per-tile partials -> out (deterministic fixed-order sum)
__global__ __launch_bounds__(256) void combine_kernel(
    const float* __restrict__ rpart, const int* __restrict__ batch,
    float* __restrict__ out, int nRows)
{
    const int g = blockIdx.x, c = threadIdx.x;
    __shared__ int srange[2];
    if (c == 0) srange[0] = lower_bound_i(batch, nRows, g);
    if (c == 1) srange[1] = lower_bound_i(batch, nRows, g + 1);
    __syncthreads();
    const int lb = srange[0], ub = srange[1];
    float sum = 0.f;
    if (lb < ub) {
        int t0 = lb >> 7, t1 = (ub - 1) >> 7;
        for (int t = t0; t <= t1; t++) {
            int base_row = t << 7;
            int s0 = batch[base_row < nRows ? base_row : nRows - 1];
            int slot = g - s0;
            if (slot == 0 || slot == 1)
                sum += rpart[((size_t)t * 2 + slot) * DIM + c];
        }
    }
    out[(size_t)g * DIM + c] = sum;
}

// ---------------- mma.sync GEMM (1 MMA per k16 tile) -------------------------
// grid(nparts, tiles): blockIdx.x = part (A L2 reuse), blockIdx.y = row tile.
// parts 0,1: cols halves of B0/bias0. parts 2,3: ATT epilogue (B1/bias1).
// rpart != nullptr: readout epilogue (no silu, weighted segment partials).
__global__ __launch_bounds__(256, 2) void gemm_mma(
    const __half* __restrict__ A,
    const __half* __restrict__ B0, const __half* __restrict__ B1,
    const float* __restrict__ bias0, const float* __restrict__ bias1,
    __half* __restrict__ Ch,
    const float* __restrict__ aW2, float* __restrict__ attp,
    const int* __restrict__ batch, const float* __restrict__ wvec,
    float* __restrict__ rpart,
    int nRows, int do_silu)
{
    extern __shared__ char sm[];
    __shared__ float s_bias[BN];
    __shared__ float s_aw2[BN];
    __shared__ float s_part[2][BM];
    __shared__ float s_w[BM];
    __shared__ int   s_seg[BM];
    __shared__ float s_red[2][2][BM];

    const int tid  = threadIdx.x;
    const int wid  = tid >> 5;
    const int lane = tid & 31;
    const int warp_m = wid >> 1;
    const int warp_n = wid & 1;
    const int part = blockIdx.x;
    const bool is_att = (part >= 2);
    const int colBase = (part & 1) * BN;
    const int rowBase = blockIdx.y * BM;

    const __half* B    = is_att ? B1 : B0;
    const float*  bias = is_att ? bias1 : bias0;

    if (tid < BN) {
        s_bias[tid] = bias[colBase + tid];
        if (is_att) s_aw2[tid] = aW2[colBase + tid];
    }
    if (rpart && tid < BM) {
        int row = rowBase + tid;
        int cr  = row < nRows ? row : nRows - 1;
        s_w[tid]   = (row < nRows) ? wvec[row] : 0.f;
        s_seg[tid] = batch[cr];
    }

    const uint32_t smb = smem_u32(sm);

    auto load_stage = [&](int s, int kt) {
        const uint32_t st = smb + s * STAGE;
        const int ke = kt * BKT;
        #pragma unroll
        for (int i = 0; i < 4; i++) {
            int f = tid + i * 256;
            int r = f >> 3, c = f & 7;
            uint32_t off = (uint32_t)(r * 128 + ((c ^ (r & 7)) << 4));
            int gr = rowBase + r; if (gr >= nRows) gr = nRows - 1;
            cp16(st + off,         A + (size_t)gr * DIM + ke + c * 8);
            cp16(st + OFF_B + off, B + (size_t)(colBase + r) * DIM + ke + c * 8);
        }
        cp_commit();
    };

    load_stage(0, 0);
    load_stage(1, 1);

    float acc[2][8][4];
    #pragma unroll
    for (int mt = 0; mt < 2; mt++)
        #pragma unroll
        for (int j = 0; j < 8; j++)
            #pragma unroll
            for (int q = 0; q < 4; q++) acc[mt][j][q] = 0.f;

    const int rrA = (lane & 7) + ((lane >> 3) & 1) * 8;
    const int khA = lane >> 4;
    const int rrB = (lane & 7) + (lane >> 4) * 8;
    const int khB = (lane >> 3) & 1;

    int sbuf = 0;
    for (int kt = 0; kt < KTILES; kt++) {
        cp_wait<1>();
        __syncthreads();
        if (kt + 2 < KTILES) {
            int ns = sbuf + 2; if (ns >= NSTAGE) ns -= NSTAGE;
            load_stage(ns, kt + 2);
        } else {
            cp_commit();
        }

        const uint32_t ast = smb + sbuf * STAGE;

        #pragma unroll
        for (int ks = 0; ks < 4; ks++) {
            const int cA = ks * 2 + khA;
            const int cB = ks * 2 + khB;
            uint32_t ah[2][4];
            #pragma unroll
            for (int mt = 0; mt < 2; mt++) {
                int row = warp_m * 32 + mt * 16 + rrA;
                ldsm4(ah[mt], ast + row * 128 + ((cA ^ (row & 7)) << 4));
            }
            #pragma unroll
            for (int nt = 0; nt < 4; nt++) {
                int row = warp_n * 64 + nt * 16 + rrB;
                uint32_t bh[4];
                ldsm4(bh, ast + OFF_B + row * 128 + ((cB ^ (row & 7)) << 4));
                #pragma unroll
                for (int mt = 0; mt < 2; mt++)
                    #pragma unroll
                    for (int h = 0; h < 2; h++)
                        mma16816(acc[mt][nt * 2 + h], ah[mt], &bh[h * 2]);
            }
        }
        if (++sbuf >= NSTAGE) sbuf = 0;
    }

    // ---- epilogue ----
    const int g  = lane >> 2;
    const int cp = (lane & 3) * 2;

    if (is_att) {
        float part2[2][2] = {{0.f, 0.f}, {0.f, 0.f}};
        #pragma unroll
        for (int mt = 0; mt < 2; mt++)
            #pragma unroll
            for (int j = 0; j < 8; j++) {
                int lc = warp_n * 64 + j * 8 + cp;
                float bz0 = s_bias[lc], bz1 = s_bias[lc + 1];
                float w0 = s_aw2[lc],  w1 = s_aw2[lc + 1];
                #pragma unroll
                for (int hrow = 0; hrow < 2; hrow++) {
                    float v0 = silu_f(acc[mt][j][hrow * 2]     + bz0);
                    float v1 = silu_f(acc[mt][j][hrow * 2 + 1] + bz1);
                    part2[mt][hrow] += v0 * w0 + v1 * w1;
                }
            }
        #pragma unroll
        for (int mt = 0; mt < 2; mt++)
            #pragma unroll
            for (int hrow = 0; hrow < 2; hrow++) {
                float p = part2[mt][hrow];
                p += __shfl_xor_sync(0xFFFFFFFFu, p, 1);
                p += __shfl_xor_sync(0xFFFFFFFFu, p, 2);
                if ((lane & 3) == 0)
                    s_part[warp_n][warp_m * 32 + mt * 16 + hrow * 8 + g] = p;
            }
        __syncthreads();
        if (tid < BM) {
            int row = rowBase + tid;
            if (row < nRows)
                attp[(size_t)(part - 2) * NMAX + row] =
                    s_part[0][tid] + s_part[1][tid];
        }
        return;
    }

    if (rpart) {
        // weighted-readout epilogue: xw[row][col] = (acc+bias)*w[row] in smem,
        // then segment-aware column sums -> per-tile partials (2 slots).
        __syncthreads();                        // ring buffers fully consumed
        float* xw = (float*)sm;                 // [128][XW_STRIDE]
        #pragma unroll
        for (int mt = 0; mt < 2; mt++) {
            #pragma unroll
            for (int j = 0; j < 8; j++) {
                int lc = warp_n * 64 + j * 8 + cp;
                float bz0 = s_bias[lc], bz1 = s_bias[lc + 1];
                #pragma unroll
                for (int hrow = 0; hrow < 2; hrow++) {
                    int lr = warp_m * 32 + mt * 16 + hrow * 8 + g;
                    float wv = s_w[lr];
                    xw[lr * XW_STRIDE + lc]     = (acc[mt][j][hrow * 2]     + bz0) * wv;
                    xw[lr * XW_STRIDE + lc + 1] = (acc[mt][j][hrow * 2 + 1] + bz1) * wv;
                }
            }
        }
        __syncthreads();
        int col  = tid & 127;
        int half = tid >> 7;
        int sbase = s_seg[0];
        float a0 = 0.f, a1 = 0.f;
        int r0 = half * 64;
        for (int r = r0; r < r0 + 64; r++) {
            float v = xw[r * XW_STRIDE + col];
            if (s_seg[r] == sbase) a0 += v; else a1 += v;
        }
        s_red[half][0][col] = a0;
        s_red[half][1][col] = a1;
        __syncthreads();
        if (tid < BM) {
            size_t base = ((size_t)blockIdx.y * 2) * DIM + colBase + tid;
            rpart[base]       = s_red[0][0][tid] + s_red[1][0][tid];
            rpart[base + DIM] = s_red[0][1][tid] + s_red[1][1][tid];
        }
        return;
    }

    #pragma unroll
    for (int mt = 0; mt < 2; mt++) {
        int row0 = rowBase + warp_m * 32 + mt * 16 + g;
        #pragma unroll
        for (int j = 0; j < 8; j++) {
            int lc = warp_n * 64 + j * 8 + cp;
            float bz0 = s_bias[lc], bz1 = s_bias[lc + 1];
            #pragma unroll
            for (int hrow = 0; hrow < 2; hrow++) {
                int row = row0 + hrow * 8;
                if (row >= nRows) continue;
                float v0 = acc[mt][j][hrow * 2]     + bz0;
                float v1 = acc[mt][j][hrow * 2 + 1] + bz1;
                if (do_silu) { v0 = silu_f(v0); v1 = silu_f(v1); }
                size_t o = (size_t)row * DIM + colBase + lc;
                *(uint32_t*)(Ch + o) = h2_as_u32(__floats2half2_rn(v0, v1));
            }
        }
    }
}

// ---------------- launch ----------------------------------------------------
extern "C" void kernel_launch(void* const* d_in, const int* in_sizes, int n_in,
                              void* d_out, int out_size)
{
    const float* X     = (const float*)d_in[0];
    const int*   batch = (const int*)d_in[1];
    const float* W1  = (const float*)d_in[3];
    const float* b1  = (const float*)d_in[4];
    const float* W2  = (const float*)d_in[5];
    const float* b2  = (const float*)d_in[6];
    const float* W3  = (const float*)d_in[7];
    const float* b3  = (const float*)d_in[8];
    const float* aW1 = (const float*)d_in[9];
    const float* ab1 = (const float*)d_in[10];
    const float* aW2 = (const float*)d_in[11];
    const float* ab2 = (const float*)d_in[12];
    float* out = (float*)d_out;

    const int N = in_sizes[0] / DIM;
    const int G = out_size / DIM;

    __half *Xh, *h1, *h2, *Wt;
    float *att, *wv, *rp;
    cudaGetSymbolAddress((void**)&Xh, g_Xh);
    cudaGetSymbolAddress((void**)&h1, g_h1);
    cudaGetSymbolAddress((void**)&h2, g_h2);
    cudaGetSymbolAddress((void**)&Wt, g_Wt);
    cudaGetSymbolAddress((void**)&att, g_att);
    cudaGetSymbolAddress((void**)&wv, g_w);
    cudaGetSymbolAddress((void**)&rp, g_rpart);

    __half* W1t = Wt + 0 * DIM * DIM;
    __half* W2t = Wt + 1 * DIM * DIM;
    __half* W3t = Wt + 2 * DIM * DIM;
    __half* WAt = Wt + 3 * DIM * DIM;

    cudaFuncSetAttribute(gemm_mma, cudaFuncAttributeMaxDynamicSharedMemorySize, DYN_SMEM);

    int n4 = N * (DIM / 4);
    xhalf_kernel<<<(n4 + 255) / 256, 256>>>((const float4*)X, (uint2*)Xh, n4);
    wtrans_all_kernel<<<dim3(DIM, 4), DIM>>>(W1, W2, W3, aW1, Wt);

    const int tiles = (N + BM - 1) / BM;

    // fused: W1 GEMM (parts 0,1 -> h1) + attention GEMM (parts 2,3 -> att)
    gemm_mma<<<dim3(4, tiles), 256, DYN_SMEM>>>(Xh, W1t, WAt, b1, ab1,
                                                h1, aW2, att,
                                                nullptr, nullptr, nullptr, N, 1);
    // softmax weights from attention partials
    weights_kernel<<<G, 256>>>(att, att + NMAX, ab2, batch, wv, N);

    // h2 = silu(h1@W2+b2)
    gemm_mma<<<dim3(2, tiles), 256, DYN_SMEM>>>(h1, W2t, W2t, b2, b2,
                                                h2, aW2, att,
                                                nullptr, nullptr, nullptr, N, 1);
    // fused x GEMM + weighted readout partials
    gemm_mma<<<dim3(2, tiles), 256, DYN_SMEM>>>(h2, W3t, W3t, b3, b3,
                                                nullptr, aW2, att,
                                                batch, wv, rp, N, 0);
    // deterministic combine -> out
    combine_kernel<<<G, 256>>>(rp, batch, out, N);
}